// round 5
// baseline (speedup 1.0000x reference)
#include <cuda_runtime.h>
#include <cuda_bf16.h>
#include <cstdint>

// ---------------------------------------------------------------------------
// GatedShortBlock via split-bf16 HMMA (mma.sync):
//   bcx = x @ w1^T   (16384 x 6144, K=2048)
//   u   = Cg * causal_conv4(Bg * Xg)
//   out = u @ w2^T   (16384 x 2048, K=2048)
// C = Ah*Bh^T + Ah*Bl^T + Al*Bh^T  (bf16 operands, fp32 accum, err ~2^-17)
// R5: inner-loop reorder -> same-accumulator reuse distance 8 MMAs
//     (was 1: three back-to-back MMAs into the same acc = RAW stalls).
// ---------------------------------------------------------------------------

#define D_MODEL 2048
#define SEQ     4096
#define MTOK    16384
#define N1      6144
#define KEL     2048
#define KT      64            // 2048 / 32 k-slabs
#define KSZ     4

// ---------------- scratch ----------------------------------------------------
__device__ __align__(16) __nv_bfloat16 g_xh [(size_t)MTOK * KEL];
__device__ __align__(16) __nv_bfloat16 g_xl [(size_t)MTOK * KEL];
__device__ __align__(16) __nv_bfloat16 g_w1h[(size_t)N1 * KEL];
__device__ __align__(16) __nv_bfloat16 g_w1l[(size_t)N1 * KEL];
__device__ __align__(16) __nv_bfloat16 g_w2h[(size_t)D_MODEL * KEL];
__device__ __align__(16) __nv_bfloat16 g_w2l[(size_t)D_MODEL * KEL];
__device__ __align__(16) __nv_bfloat16 g_uh [(size_t)MTOK * KEL];
__device__ __align__(16) __nv_bfloat16 g_ul [(size_t)MTOK * KEL];
__device__ float g_bcx[(size_t)MTOK * N1];

// ---------------- asm helpers ------------------------------------------------
__device__ __forceinline__ uint32_t smem_u32(const void* p) {
    uint32_t a;
    asm("{ .reg .u64 t; cvta.to.shared.u64 t, %1; cvt.u32.u64 %0, t; }" : "=r"(a) : "l"(p));
    return a;
}
__device__ __forceinline__ void cp16(uint32_t dst, const void* src) {
    asm volatile("cp.async.cg.shared.global [%0], [%1], 16;" :: "r"(dst), "l"(src));
}
#define CP_COMMIT() asm volatile("cp.async.commit_group;" ::: "memory")
#define CP_WAIT2()  asm volatile("cp.async.wait_group 2;" ::: "memory")

#define LDSM_X4(r0, r1, r2, r3, addr) \
    asm volatile("ldmatrix.sync.aligned.m8n8.x4.shared.b16 {%0,%1,%2,%3}, [%4];" \
        : "=r"(r0), "=r"(r1), "=r"(r2), "=r"(r3) : "r"(addr))

// NOTE: not volatile — register-only op; lets ptxas interleave MMAs.
#define MMA16816(c, a0, a1, a2, a3, b0, b1) \
    asm("mma.sync.aligned.m16n8k16.row.col.f32.bf16.bf16.f32 " \
        "{%0,%1,%2,%3}, {%4,%5,%6,%7}, {%8,%9}, {%0,%1,%2,%3};" \
        : "+f"((c)[0]), "+f"((c)[1]), "+f"((c)[2]), "+f"((c)[3]) \
        : "r"(a0), "r"(a1), "r"(a2), "r"(a3), "r"(b0), "r"(b1))

// ---------------------------------------------------------------------------
// GEMM kernel. Smem per stage (48KB): [Ah 8K | Al 8K | Bh 16K | Bl 16K],
// rows are 64B (32 K-elems), 16B chunks XOR-swizzled by ((row>>1)&3).
// ---------------------------------------------------------------------------
#define STAGE_B   49152
#define GEMM_SMEM (4 * STAGE_B)   // 196608

__global__ __launch_bounds__(256, 1) void gemm_split(
    const __nv_bfloat16* __restrict__ Ah, const __nv_bfloat16* __restrict__ Al,
    const __nv_bfloat16* __restrict__ Bh, const __nv_bfloat16* __restrict__ Bl,
    float* __restrict__ C, int Ntot)
{
    extern __shared__ __align__(1024) char smem[];
    const uint32_t sb = smem_u32(smem);
    const int tid  = threadIdx.x;
    const int lane = tid & 31;
    const int wid  = tid >> 5;
    const int wm   = wid >> 2;        // 0..1  (m)
    const int wn   = wid & 3;         // 0..3  (n)

    const size_t m0 = (size_t)blockIdx.y * 128;
    const size_t n0 = (size_t)blockIdx.x * 256;

    const char* pAh = (const char*)(Ah + m0 * (size_t)KEL);
    const char* pAl = (const char*)(Al + m0 * (size_t)KEL);
    const char* pBh = (const char*)(Bh + n0 * (size_t)KEL);
    const char* pBl = (const char*)(Bl + n0 * (size_t)KEL);

    auto load_stage = [&](int s, int kt) {
        const uint32_t st = sb + s * STAGE_B;
        const size_t kb = (size_t)kt * 64;   // byte offset along K
        #pragma unroll
        for (int rep = 0; rep < 2; rep++) {          // A: 128 rows x 4 chunks
            const int idx = rep * 256 + tid;
            const int row = idx >> 2, c = idx & 3;
            const uint32_t d = st + row * 64 + ((((uint32_t)c) ^ ((row >> 1) & 3)) << 4);
            const size_t so = (size_t)row * (KEL * 2) + kb + c * 16;
            cp16(d,        pAh + so);
            cp16(d + 8192, pAl + so);
        }
        #pragma unroll
        for (int rep = 0; rep < 4; rep++) {          // B: 256 rows x 4 chunks
            const int idx = rep * 256 + tid;
            const int row = idx >> 2, c = idx & 3;
            const uint32_t d = st + 16384 + row * 64 + ((((uint32_t)c) ^ ((row >> 1) & 3)) << 4);
            const size_t so = (size_t)row * (KEL * 2) + kb + c * 16;
            cp16(d,         pBh + so);
            cp16(d + 16384, pBl + so);
        }
    };

    load_stage(0, 0); CP_COMMIT();
    load_stage(1, 1); CP_COMMIT();
    load_stage(2, 2); CP_COMMIT();

    float acc[4][8][4];
    #pragma unroll
    for (int i = 0; i < 4; i++)
        #pragma unroll
        for (int j = 0; j < 8; j++)
            #pragma unroll
            for (int q = 0; q < 4; q++) acc[i][j][q] = 0.0f;

    const int lrow8  = lane & 7;
    const int lhalfA = (lane >> 3) & 1;
    const int lkA    = lane >> 4;
    const int lhalfB = lane >> 4;
    const int lkB    = (lane >> 3) & 1;

    for (int kt = 0; kt < KT; kt++) {
        CP_WAIT2();
        __syncthreads();
        if (kt + 3 < KT) load_stage((kt + 3) & 3, kt + 3);
        CP_COMMIT();

        const uint32_t st = sb + (kt & 3) * STAGE_B;
        #pragma unroll
        for (int ks = 0; ks < 2; ks++) {
            const int kc = ks * 2;
            uint32_t ahf[4][4], alf[4][4];
            #pragma unroll
            for (int i = 0; i < 4; i++) {
                const int row = wm * 64 + i * 16 + lrow8 + lhalfA * 8;
                const uint32_t ad = st + row * 64 +
                    ((((uint32_t)(kc + lkA)) ^ ((row >> 1) & 3)) << 4);
                LDSM_X4(ahf[i][0], ahf[i][1], ahf[i][2], ahf[i][3], ad);
                LDSM_X4(alf[i][0], alf[i][1], alf[i][2], alf[i][3], ad + 8192);
            }
            #pragma unroll
            for (int jp = 0; jp < 4; jp++) {
                const int nrow = wn * 64 + jp * 16 + lrow8 + lhalfB * 8;
                const uint32_t bd = st + 16384 + nrow * 64 +
                    ((((uint32_t)(kc + lkB)) ^ ((nrow >> 1) & 3)) << 4);
                uint32_t bh0, bh1, bh2, bh3, bl0, bl1, bl2, bl3;
                LDSM_X4(bh0, bh1, bh2, bh3, bd);
                LDSM_X4(bl0, bl1, bl2, bl3, bd + 16384);
                // Reordered: i innermost per product -> same-acc reuse
                // distance = 8 MMAs (was 1).
                #pragma unroll
                for (int i = 0; i < 4; i++)
                    MMA16816(acc[i][jp * 2],     ahf[i][0], ahf[i][1], ahf[i][2], ahf[i][3], bh0, bh1);
                #pragma unroll
                for (int i = 0; i < 4; i++)
                    MMA16816(acc[i][jp * 2 + 1], ahf[i][0], ahf[i][1], ahf[i][2], ahf[i][3], bh2, bh3);
                #pragma unroll
                for (int i = 0; i < 4; i++)
                    MMA16816(acc[i][jp * 2],     ahf[i][0], ahf[i][1], ahf[i][2], ahf[i][3], bl0, bl1);
                #pragma unroll
                for (int i = 0; i < 4; i++)
                    MMA16816(acc[i][jp * 2 + 1], ahf[i][0], ahf[i][1], ahf[i][2], ahf[i][3], bl2, bl3);
                #pragma unroll
                for (int i = 0; i < 4; i++)
                    MMA16816(acc[i][jp * 2],     alf[i][0], alf[i][1], alf[i][2], alf[i][3], bh0, bh1);
                #pragma unroll
                for (int i = 0; i < 4; i++)
                    MMA16816(acc[i][jp * 2 + 1], alf[i][0], alf[i][1], alf[i][2], alf[i][3], bh2, bh3);
            }
        }
    }

    // ---- epilogue -----------------------------------------------------------
    #pragma unroll
    for (int i = 0; i < 4; i++) {
        const size_t r = m0 + wm * 64 + i * 16 + (lane >> 2);
        #pragma unroll
        for (int j = 0; j < 8; j++) {
            const size_t c = n0 + wn * 64 + j * 8 + (lane & 3) * 2;
            *reinterpret_cast<float2*>(C + r * (size_t)Ntot + c) =
                make_float2(acc[i][j][0], acc[i][j][1]);
            *reinterpret_cast<float2*>(C + (r + 8) * (size_t)Ntot + c) =
                make_float2(acc[i][j][2], acc[i][j][3]);
        }
    }
}

// ---------------------------------------------------------------------------
// fp32 -> (hi, lo) bf16 split, elementwise. 8 elements per thread.
// ---------------------------------------------------------------------------
__global__ __launch_bounds__(256) void split_bf16(
    const float* __restrict__ src, __nv_bfloat16* __restrict__ hi,
    __nv_bfloat16* __restrict__ lo, size_t total8)
{
    size_t idx = (size_t)blockIdx.x * blockDim.x + threadIdx.x;
    if (idx >= total8) return;
    const float* s = src + idx * 8;
    float4 v0 = *reinterpret_cast<const float4*>(s);
    float4 v1 = *reinterpret_cast<const float4*>(s + 4);
    float v[8] = {v0.x, v0.y, v0.z, v0.w, v1.x, v1.y, v1.z, v1.w};
    union { __nv_bfloat16 h[8]; uint4 u; } H, L;
    #pragma unroll
    for (int i = 0; i < 8; i++) {
        __nv_bfloat16 h = __float2bfloat16(v[i]);
        H.h[i] = h;
        L.h[i] = __float2bfloat16(v[i] - __bfloat162float(h));
    }
    *reinterpret_cast<uint4*>(hi + idx * 8) = H.u;
    *reinterpret_cast<uint4*>(lo + idx * 8) = L.u;
}

// ---------------------------------------------------------------------------
// Fused gate + causal depthwise conv(K=4) + gate; outputs split bf16 u.
// ---------------------------------------------------------------------------
__global__ __launch_bounds__(256) void conv_gate_split(
    const float* __restrict__ bcx, const float* __restrict__ cw,
    __nv_bfloat16* __restrict__ uh, __nv_bfloat16* __restrict__ ul)
{
    size_t idx = (size_t)blockIdx.x * blockDim.x + threadIdx.x;
    if (idx >= (size_t)MTOK * 256) return;
    const int g = (int)(idx & 255);
    const size_t m = idx >> 8;
    const int d0 = g * 8;
    const int s = (int)(m % SEQ);

    float w[8][4];
    #pragma unroll
    for (int j = 0; j < 8; j++) {
        float4 wv = *reinterpret_cast<const float4*>(cw + (size_t)(d0 + j) * 4);
        w[j][0] = wv.x; w[j][1] = wv.y; w[j][2] = wv.z; w[j][3] = wv.w;
    }

    float acc[8] = {0, 0, 0, 0, 0, 0, 0, 0};
    #pragma unroll
    for (int back = 0; back < 4; back++) {
        if (s - back >= 0) {
            const float* row = bcx + (m - back) * (size_t)N1;
            float4 b0 = *reinterpret_cast<const float4*>(row + d0);
            float4 b1 = *reinterpret_cast<const float4*>(row + d0 + 4);
            float4 x0 = *reinterpret_cast<const float4*>(row + 2 * D_MODEL + d0);
            float4 x1 = *reinterpret_cast<const float4*>(row + 2 * D_MODEL + d0 + 4);
            float bb[8] = {b0.x, b0.y, b0.z, b0.w, b1.x, b1.y, b1.z, b1.w};
            float xx[8] = {x0.x, x0.y, x0.z, x0.w, x1.x, x1.y, x1.z, x1.w};
            #pragma unroll
            for (int j = 0; j < 8; j++)
                acc[j] = fmaf(bb[j] * xx[j], w[j][3 - back], acc[j]);
        }
    }
    const float* crow = bcx + m * (size_t)N1 + D_MODEL;
    float4 c0 = *reinterpret_cast<const float4*>(crow + d0);
    float4 c1 = *reinterpret_cast<const float4*>(crow + d0 + 4);
    float cc[8] = {c0.x, c0.y, c0.z, c0.w, c1.x, c1.y, c1.z, c1.w};

    union { __nv_bfloat16 h[8]; uint4 u; } H, L;
    #pragma unroll
    for (int j = 0; j < 8; j++) {
        float u = cc[j] * acc[j];
        __nv_bfloat16 h = __float2bfloat16(u);
        H.h[j] = h;
        L.h[j] = __float2bfloat16(u - __bfloat162float(h));
    }
    const size_t off = m * (size_t)D_MODEL + d0;
    *reinterpret_cast<uint4*>(uh + off) = H.u;
    *reinterpret_cast<uint4*>(ul + off) = L.u;
}

// ---------------------------------------------------------------------------
extern "C" void kernel_launch(void* const* d_in, const int* in_sizes, int n_in,
                              void* d_out, int out_size)
{
    const float* x  = (const float*)d_in[0];
    const float* w1 = (const float*)d_in[1];
    const float* w2 = (const float*)d_in[2];
    const float* cw = (const float*)d_in[3];
    float* out = (float*)d_out;

    __nv_bfloat16 *xh, *xl, *w1h, *w1l, *w2h, *w2l, *uh, *ul;
    float* bcx;
    cudaGetSymbolAddress((void**)&xh,  g_xh);
    cudaGetSymbolAddress((void**)&xl,  g_xl);
    cudaGetSymbolAddress((void**)&w1h, g_w1h);
    cudaGetSymbolAddress((void**)&w1l, g_w1l);
    cudaGetSymbolAddress((void**)&w2h, g_w2h);
    cudaGetSymbolAddress((void**)&w2l, g_w2l);
    cudaGetSymbolAddress((void**)&uh,  g_uh);
    cudaGetSymbolAddress((void**)&ul,  g_ul);
    cudaGetSymbolAddress((void**)&bcx, g_bcx);

    cudaFuncSetAttribute(gemm_split,
                         cudaFuncAttributeMaxDynamicSharedMemorySize, GEMM_SMEM);

    split_bf16<<<(int)(((size_t)MTOK * KEL / 8 + 255) / 256), 256>>>(
        x, xh, xl, (size_t)MTOK * KEL / 8);
    split_bf16<<<(int)(((size_t)N1 * KEL / 8 + 255) / 256), 256>>>(
        w1, w1h, w1l, (size_t)N1 * KEL / 8);
    split_bf16<<<(int)(((size_t)D_MODEL * KEL / 8 + 255) / 256), 256>>>(
        w2, w2h, w2l, (size_t)D_MODEL * KEL / 8);

    // GEMM1: bcx = x @ w1^T
    {
        dim3 grid(N1 / 256, MTOK / 128);
        gemm_split<<<grid, 256, GEMM_SMEM>>>(xh, xl, w1h, w1l, bcx, N1);
    }

    conv_gate_split<<<MTOK * 256 / 256, 256>>>(bcx, cw, uh, ul);

    // GEMM2: out = u @ w2^T
    {
        dim3 grid(D_MODEL / 256, MTOK / 128);
        gemm_split<<<grid, 256, GEMM_SMEM>>>(uh, ul, w2h, w2l, out, D_MODEL);
    }
}

// round 6
// speedup vs baseline: 1.0113x; 1.0113x over previous
#include <cuda_runtime.h>
#include <cuda_bf16.h>
#include <cstdint>

// ---------------------------------------------------------------------------
// GatedShortBlock via split-bf16 HMMA (mma.sync):
//   bcx = x @ w1^T   (16384 x 6144, K=2048)
//   u   = Cg * causal_conv4(Bg * Xg)
//   out = u @ w2^T   (16384 x 2048, K=2048)
// C = Ah*Bh^T + Ah*Bl^T + Al*Bh^T  (bf16 operands, fp32 accum, err ~2^-17)
// R6: 512 threads (16 warps, 4x4 grid, warp tile 32x64) -> 4 warps/SMSP for
//     LDSM latency hiding. MMA ordering + volatile reverted to R4 (R5 regressed).
// ---------------------------------------------------------------------------

#define D_MODEL 2048
#define SEQ     4096
#define MTOK    16384
#define N1      6144
#define KEL     2048
#define KT      64            // 2048 / 32 k-slabs
#define KSZ     4

// ---------------- scratch ----------------------------------------------------
__device__ __align__(16) __nv_bfloat16 g_xh [(size_t)MTOK * KEL];
__device__ __align__(16) __nv_bfloat16 g_xl [(size_t)MTOK * KEL];
__device__ __align__(16) __nv_bfloat16 g_w1h[(size_t)N1 * KEL];
__device__ __align__(16) __nv_bfloat16 g_w1l[(size_t)N1 * KEL];
__device__ __align__(16) __nv_bfloat16 g_w2h[(size_t)D_MODEL * KEL];
__device__ __align__(16) __nv_bfloat16 g_w2l[(size_t)D_MODEL * KEL];
__device__ __align__(16) __nv_bfloat16 g_uh [(size_t)MTOK * KEL];
__device__ __align__(16) __nv_bfloat16 g_ul [(size_t)MTOK * KEL];
__device__ float g_bcx[(size_t)MTOK * N1];

// ---------------- asm helpers ------------------------------------------------
__device__ __forceinline__ uint32_t smem_u32(const void* p) {
    uint32_t a;
    asm("{ .reg .u64 t; cvta.to.shared.u64 t, %1; cvt.u32.u64 %0, t; }" : "=r"(a) : "l"(p));
    return a;
}
__device__ __forceinline__ void cp16(uint32_t dst, const void* src) {
    asm volatile("cp.async.cg.shared.global [%0], [%1], 16;" :: "r"(dst), "l"(src));
}
#define CP_COMMIT() asm volatile("cp.async.commit_group;" ::: "memory")
#define CP_WAIT2()  asm volatile("cp.async.wait_group 2;" ::: "memory")

#define LDSM_X4(r0, r1, r2, r3, addr) \
    asm volatile("ldmatrix.sync.aligned.m8n8.x4.shared.b16 {%0,%1,%2,%3}, [%4];" \
        : "=r"(r0), "=r"(r1), "=r"(r2), "=r"(r3) : "r"(addr))

#define MMA16816(c, a0, a1, a2, a3, b0, b1) \
    asm volatile("mma.sync.aligned.m16n8k16.row.col.f32.bf16.bf16.f32 " \
        "{%0,%1,%2,%3}, {%4,%5,%6,%7}, {%8,%9}, {%0,%1,%2,%3};" \
        : "+f"((c)[0]), "+f"((c)[1]), "+f"((c)[2]), "+f"((c)[3]) \
        : "r"(a0), "r"(a1), "r"(a2), "r"(a3), "r"(b0), "r"(b1))

// ---------------------------------------------------------------------------
// GEMM kernel. Smem per stage (48KB): [Ah 8K | Al 8K | Bh 16K | Bl 16K],
// rows are 64B (32 K-elems), 16B chunks XOR-swizzled by ((row>>1)&3).
// CTA tile 128x256, 512 threads, warp grid 4(m) x 4(n), warp tile 32x64.
// ---------------------------------------------------------------------------
#define STAGE_B   49152
#define GEMM_SMEM (4 * STAGE_B)   // 196608

__global__ __launch_bounds__(512, 1) void gemm_split(
    const __nv_bfloat16* __restrict__ Ah, const __nv_bfloat16* __restrict__ Al,
    const __nv_bfloat16* __restrict__ Bh, const __nv_bfloat16* __restrict__ Bl,
    float* __restrict__ C, int Ntot)
{
    extern __shared__ __align__(1024) char smem[];
    const uint32_t sb = smem_u32(smem);
    const int tid  = threadIdx.x;
    const int lane = tid & 31;
    const int wid  = tid >> 5;
    const int wm   = wid >> 2;        // 0..3  (m)
    const int wn   = wid & 3;         // 0..3  (n)

    const size_t m0 = (size_t)blockIdx.y * 128;
    const size_t n0 = (size_t)blockIdx.x * 256;

    const char* pAh = (const char*)(Ah + m0 * (size_t)KEL);
    const char* pAl = (const char*)(Al + m0 * (size_t)KEL);
    const char* pBh = (const char*)(Bh + n0 * (size_t)KEL);
    const char* pBl = (const char*)(Bl + n0 * (size_t)KEL);

    auto load_stage = [&](int s, int kt) {
        const uint32_t st = sb + s * STAGE_B;
        const size_t kb = (size_t)kt * 64;   // byte offset along K
        {   // A: 128 rows x 4 chunks = 512 -> 1 per thread
            const int row = tid >> 2, c = tid & 3;
            const uint32_t d = st + row * 64 + ((((uint32_t)c) ^ ((row >> 1) & 3)) << 4);
            const size_t so = (size_t)row * (KEL * 2) + kb + c * 16;
            cp16(d,        pAh + so);
            cp16(d + 8192, pAl + so);
        }
        #pragma unroll
        for (int rep = 0; rep < 2; rep++) {   // B: 256 rows x 4 chunks = 1024 -> 2 per thread
            const int idx = rep * 512 + tid;
            const int row = idx >> 2, c = idx & 3;
            const uint32_t d = st + 16384 + row * 64 + ((((uint32_t)c) ^ ((row >> 1) & 3)) << 4);
            const size_t so = (size_t)row * (KEL * 2) + kb + c * 16;
            cp16(d,         pBh + so);
            cp16(d + 16384, pBl + so);
        }
    };

    load_stage(0, 0); CP_COMMIT();
    load_stage(1, 1); CP_COMMIT();
    load_stage(2, 2); CP_COMMIT();

    float acc[2][8][4];
    #pragma unroll
    for (int i = 0; i < 2; i++)
        #pragma unroll
        for (int j = 0; j < 8; j++)
            #pragma unroll
            for (int q = 0; q < 4; q++) acc[i][j][q] = 0.0f;

    const int lrow8  = lane & 7;
    const int lhalfA = (lane >> 3) & 1;
    const int lkA    = lane >> 4;
    const int lhalfB = lane >> 4;
    const int lkB    = (lane >> 3) & 1;

    for (int kt = 0; kt < KT; kt++) {
        CP_WAIT2();
        __syncthreads();
        if (kt + 3 < KT) load_stage((kt + 3) & 3, kt + 3);
        CP_COMMIT();

        const uint32_t st = sb + (kt & 3) * STAGE_B;
        #pragma unroll
        for (int ks = 0; ks < 2; ks++) {
            const int kc = ks * 2;
            uint32_t ahf[2][4], alf[2][4];
            #pragma unroll
            for (int i = 0; i < 2; i++) {
                const int row = wm * 32 + i * 16 + lrow8 + lhalfA * 8;
                const uint32_t ad = st + row * 64 +
                    ((((uint32_t)(kc + lkA)) ^ ((row >> 1) & 3)) << 4);
                LDSM_X4(ahf[i][0], ahf[i][1], ahf[i][2], ahf[i][3], ad);
                LDSM_X4(alf[i][0], alf[i][1], alf[i][2], alf[i][3], ad + 8192);
            }
            #pragma unroll
            for (int jp = 0; jp < 4; jp++) {
                const int nrow = wn * 64 + jp * 16 + lrow8 + lhalfB * 8;
                const uint32_t bd = st + 16384 + nrow * 64 +
                    ((((uint32_t)(kc + lkB)) ^ ((nrow >> 1) & 3)) << 4);
                uint32_t bh0, bh1, bh2, bh3, bl0, bl1, bl2, bl3;
                LDSM_X4(bh0, bh1, bh2, bh3, bd);
                LDSM_X4(bl0, bl1, bl2, bl3, bd + 16384);
                #pragma unroll
                for (int i = 0; i < 2; i++) {
                    float* c0 = acc[i][jp * 2];
                    float* c1 = acc[i][jp * 2 + 1];
                    MMA16816(c0, ahf[i][0], ahf[i][1], ahf[i][2], ahf[i][3], bh0, bh1);
                    MMA16816(c0, ahf[i][0], ahf[i][1], ahf[i][2], ahf[i][3], bl0, bl1);
                    MMA16816(c0, alf[i][0], alf[i][1], alf[i][2], alf[i][3], bh0, bh1);
                    MMA16816(c1, ahf[i][0], ahf[i][1], ahf[i][2], ahf[i][3], bh2, bh3);
                    MMA16816(c1, ahf[i][0], ahf[i][1], ahf[i][2], ahf[i][3], bl2, bl3);
                    MMA16816(c1, alf[i][0], alf[i][1], alf[i][2], alf[i][3], bh2, bh3);
                }
            }
        }
    }

    // ---- epilogue -----------------------------------------------------------
    #pragma unroll
    for (int i = 0; i < 2; i++) {
        const size_t r = m0 + wm * 32 + i * 16 + (lane >> 2);
        #pragma unroll
        for (int j = 0; j < 8; j++) {
            const size_t c = n0 + wn * 64 + j * 8 + (lane & 3) * 2;
            *reinterpret_cast<float2*>(C + r * (size_t)Ntot + c) =
                make_float2(acc[i][j][0], acc[i][j][1]);
            *reinterpret_cast<float2*>(C + (r + 8) * (size_t)Ntot + c) =
                make_float2(acc[i][j][2], acc[i][j][3]);
        }
    }
}

// ---------------------------------------------------------------------------
// fp32 -> (hi, lo) bf16 split, elementwise. 8 elements per thread.
// ---------------------------------------------------------------------------
__global__ __launch_bounds__(256) void split_bf16(
    const float* __restrict__ src, __nv_bfloat16* __restrict__ hi,
    __nv_bfloat16* __restrict__ lo, size_t total8)
{
    size_t idx = (size_t)blockIdx.x * blockDim.x + threadIdx.x;
    if (idx >= total8) return;
    const float* s = src + idx * 8;
    float4 v0 = *reinterpret_cast<const float4*>(s);
    float4 v1 = *reinterpret_cast<const float4*>(s + 4);
    float v[8] = {v0.x, v0.y, v0.z, v0.w, v1.x, v1.y, v1.z, v1.w};
    union { __nv_bfloat16 h[8]; uint4 u; } H, L;
    #pragma unroll
    for (int i = 0; i < 8; i++) {
        __nv_bfloat16 h = __float2bfloat16(v[i]);
        H.h[i] = h;
        L.h[i] = __float2bfloat16(v[i] - __bfloat162float(h));
    }
    *reinterpret_cast<uint4*>(hi + idx * 8) = H.u;
    *reinterpret_cast<uint4*>(lo + idx * 8) = L.u;
}

// ---------------------------------------------------------------------------
// Fused gate + causal depthwise conv(K=4) + gate; outputs split bf16 u.
// ---------------------------------------------------------------------------
__global__ __launch_bounds__(256) void conv_gate_split(
    const float* __restrict__ bcx, const float* __restrict__ cw,
    __nv_bfloat16* __restrict__ uh, __nv_bfloat16* __restrict__ ul)
{
    size_t idx = (size_t)blockIdx.x * blockDim.x + threadIdx.x;
    if (idx >= (size_t)MTOK * 256) return;
    const int g = (int)(idx & 255);
    const size_t m = idx >> 8;
    const int d0 = g * 8;
    const int s = (int)(m % SEQ);

    float w[8][4];
    #pragma unroll
    for (int j = 0; j < 8; j++) {
        float4 wv = *reinterpret_cast<const float4*>(cw + (size_t)(d0 + j) * 4);
        w[j][0] = wv.x; w[j][1] = wv.y; w[j][2] = wv.z; w[j][3] = wv.w;
    }

    float acc[8] = {0, 0, 0, 0, 0, 0, 0, 0};
    #pragma unroll
    for (int back = 0; back < 4; back++) {
        if (s - back >= 0) {
            const float* row = bcx + (m - back) * (size_t)N1;
            float4 b0 = *reinterpret_cast<const float4*>(row + d0);
            float4 b1 = *reinterpret_cast<const float4*>(row + d0 + 4);
            float4 x0 = *reinterpret_cast<const float4*>(row + 2 * D_MODEL + d0);
            float4 x1 = *reinterpret_cast<const float4*>(row + 2 * D_MODEL + d0 + 4);
            float bb[8] = {b0.x, b0.y, b0.z, b0.w, b1.x, b1.y, b1.z, b1.w};
            float xx[8] = {x0.x, x0.y, x0.z, x0.w, x1.x, x1.y, x1.z, x1.w};
            #pragma unroll
            for (int j = 0; j < 8; j++)
                acc[j] = fmaf(bb[j] * xx[j], w[j][3 - back], acc[j]);
        }
    }
    const float* crow = bcx + m * (size_t)N1 + D_MODEL;
    float4 c0 = *reinterpret_cast<const float4*>(crow + d0);
    float4 c1 = *reinterpret_cast<const float4*>(crow + d0 + 4);
    float cc[8] = {c0.x, c0.y, c0.z, c0.w, c1.x, c1.y, c1.z, c1.w};

    union { __nv_bfloat16 h[8]; uint4 u; } H, L;
    #pragma unroll
    for (int j = 0; j < 8; j++) {
        float u = cc[j] * acc[j];
        __nv_bfloat16 h = __float2bfloat16(u);
        H.h[j] = h;
        L.h[j] = __float2bfloat16(u - __bfloat162float(h));
    }
    const size_t off = m * (size_t)D_MODEL + d0;
    *reinterpret_cast<uint4*>(uh + off) = H.u;
    *reinterpret_cast<uint4*>(ul + off) = L.u;
}

// ---------------------------------------------------------------------------
extern "C" void kernel_launch(void* const* d_in, const int* in_sizes, int n_in,
                              void* d_out, int out_size)
{
    const float* x  = (const float*)d_in[0];
    const float* w1 = (const float*)d_in[1];
    const float* w2 = (const float*)d_in[2];
    const float* cw = (const float*)d_in[3];
    float* out = (float*)d_out;

    __nv_bfloat16 *xh, *xl, *w1h, *w1l, *w2h, *w2l, *uh, *ul;
    float* bcx;
    cudaGetSymbolAddress((void**)&xh,  g_xh);
    cudaGetSymbolAddress((void**)&xl,  g_xl);
    cudaGetSymbolAddress((void**)&w1h, g_w1h);
    cudaGetSymbolAddress((void**)&w1l, g_w1l);
    cudaGetSymbolAddress((void**)&w2h, g_w2h);
    cudaGetSymbolAddress((void**)&w2l, g_w2l);
    cudaGetSymbolAddress((void**)&uh,  g_uh);
    cudaGetSymbolAddress((void**)&ul,  g_ul);
    cudaGetSymbolAddress((void**)&bcx, g_bcx);

    cudaFuncSetAttribute(gemm_split,
                         cudaFuncAttributeMaxDynamicSharedMemorySize, GEMM_SMEM);

    split_bf16<<<(int)(((size_t)MTOK * KEL / 8 + 255) / 256), 256>>>(
        x, xh, xl, (size_t)MTOK * KEL / 8);
    split_bf16<<<(int)(((size_t)N1 * KEL / 8 + 255) / 256), 256>>>(
        w1, w1h, w1l, (size_t)N1 * KEL / 8);
    split_bf16<<<(int)(((size_t)D_MODEL * KEL / 8 + 255) / 256), 256>>>(
        w2, w2h, w2l, (size_t)D_MODEL * KEL / 8);

    // GEMM1: bcx = x @ w1^T
    {
        dim3 grid(N1 / 256, MTOK / 128);
        gemm_split<<<grid, 512, GEMM_SMEM>>>(xh, xl, w1h, w1l, bcx, N1);
    }

    conv_gate_split<<<MTOK * 256 / 256, 256>>>(bcx, cw, uh, ul);

    // GEMM2: out = u @ w2^T
    {
        dim3 grid(D_MODEL / 256, MTOK / 128);
        gemm_split<<<grid, 512, GEMM_SMEM>>>(uh, ul, w2h, w2l, out, D_MODEL);
    }
}

// round 8
// speedup vs baseline: 1.0970x; 1.0848x over previous
#include <cuda_runtime.h>
#include <cuda_bf16.h>
#include <cstdint>

// ---------------------------------------------------------------------------
// GatedShortBlock via split-bf16 HMMA (mma.sync):
//   bcx = x @ w1^T   (16384 x 6144, K=2048)
//   u   = Cg * causal_conv4(Bg * Xg)
//   out = u @ w2^T   (16384 x 2048, K=2048)
// C = Ah*Bh^T + Ah*Bl^T + Al*Bh^T  (bf16 operands, fp32 accum, err ~2^-17)
// R8: R7 (128x128 tile, 2 CTAs/SM) with the 3-stage pipeline race fixed:
//     prologue loads 2 stages, wait_group 1, prefetch kt+2 -> (kt+2)%3
//     (R7 wrongly prefetched kt+3 -> same stage as the one being consumed).
// ---------------------------------------------------------------------------

#define D_MODEL 2048
#define SEQ     4096
#define MTOK    16384
#define N1      6144
#define KEL     2048
#define KT      64            // 2048 / 32 k-slabs
#define KSZ     4

// ---------------- scratch ----------------------------------------------------
__device__ __align__(16) __nv_bfloat16 g_xh [(size_t)MTOK * KEL];
__device__ __align__(16) __nv_bfloat16 g_xl [(size_t)MTOK * KEL];
__device__ __align__(16) __nv_bfloat16 g_w1h[(size_t)N1 * KEL];
__device__ __align__(16) __nv_bfloat16 g_w1l[(size_t)N1 * KEL];
__device__ __align__(16) __nv_bfloat16 g_w2h[(size_t)D_MODEL * KEL];
__device__ __align__(16) __nv_bfloat16 g_w2l[(size_t)D_MODEL * KEL];
__device__ __align__(16) __nv_bfloat16 g_uh [(size_t)MTOK * KEL];
__device__ __align__(16) __nv_bfloat16 g_ul [(size_t)MTOK * KEL];
__device__ float g_bcx[(size_t)MTOK * N1];

// ---------------- asm helpers ------------------------------------------------
__device__ __forceinline__ uint32_t smem_u32(const void* p) {
    uint32_t a;
    asm("{ .reg .u64 t; cvta.to.shared.u64 t, %1; cvt.u32.u64 %0, t; }" : "=r"(a) : "l"(p));
    return a;
}
__device__ __forceinline__ void cp16(uint32_t dst, const void* src) {
    asm volatile("cp.async.cg.shared.global [%0], [%1], 16;" :: "r"(dst), "l"(src));
}
#define CP_COMMIT() asm volatile("cp.async.commit_group;" ::: "memory")
#define CP_WAIT1()  asm volatile("cp.async.wait_group 1;" ::: "memory")

#define LDSM_X4(r0, r1, r2, r3, addr) \
    asm volatile("ldmatrix.sync.aligned.m8n8.x4.shared.b16 {%0,%1,%2,%3}, [%4];" \
        : "=r"(r0), "=r"(r1), "=r"(r2), "=r"(r3) : "r"(addr))

#define MMA16816(c, a0, a1, a2, a3, b0, b1) \
    asm volatile("mma.sync.aligned.m16n8k16.row.col.f32.bf16.bf16.f32 " \
        "{%0,%1,%2,%3}, {%4,%5,%6,%7}, {%8,%9}, {%0,%1,%2,%3};" \
        : "+f"((c)[0]), "+f"((c)[1]), "+f"((c)[2]), "+f"((c)[3]) \
        : "r"(a0), "r"(a1), "r"(a2), "r"(a3), "r"(b0), "r"(b1))

// ---------------------------------------------------------------------------
// GEMM kernel. CTA tile 128x128, 256 threads, warp grid 2(m) x 4(n),
// warp tile 64x32. Smem per stage (32KB): [Ah 8K | Al 8K | Bh 8K | Bl 8K],
// rows are 64B (32 K-elems), 16B chunks XOR-swizzled by ((row>>1)&3).
// 3 stages = 96KB -> 2 CTAs/SM.
// ---------------------------------------------------------------------------
#define STAGE_B   32768
#define GEMM_SMEM (3 * STAGE_B)   // 98304

__global__ __launch_bounds__(256, 2) void gemm_split(
    const __nv_bfloat16* __restrict__ Ah, const __nv_bfloat16* __restrict__ Al,
    const __nv_bfloat16* __restrict__ Bh, const __nv_bfloat16* __restrict__ Bl,
    float* __restrict__ C, int Ntot)
{
    extern __shared__ __align__(1024) char smem[];
    const uint32_t sb = smem_u32(smem);
    const int tid  = threadIdx.x;
    const int lane = tid & 31;
    const int wid  = tid >> 5;
    const int wm   = wid >> 2;        // 0..1  (m)
    const int wn   = wid & 3;         // 0..3  (n)

    const size_t m0 = (size_t)blockIdx.y * 128;
    const size_t n0 = (size_t)blockIdx.x * 128;

    const char* pAh = (const char*)(Ah + m0 * (size_t)KEL);
    const char* pAl = (const char*)(Al + m0 * (size_t)KEL);
    const char* pBh = (const char*)(Bh + n0 * (size_t)KEL);
    const char* pBl = (const char*)(Bl + n0 * (size_t)KEL);

    auto load_stage = [&](int s, int kt) {
        const uint32_t st = sb + s * STAGE_B;
        const size_t kb = (size_t)kt * 64;   // byte offset along K
        #pragma unroll
        for (int rep = 0; rep < 2; rep++) {   // 128 rows x 4 chunks = 512 slots
            const int idx = rep * 256 + tid;
            const int row = idx >> 2, c = idx & 3;
            const uint32_t sw = ((((uint32_t)c) ^ ((row >> 1) & 3)) << 4);
            const uint32_t dA = st + row * 64 + sw;
            const uint32_t dB = st + 16384 + row * 64 + sw;
            const size_t so = (size_t)row * (KEL * 2) + kb + c * 16;
            cp16(dA,        pAh + so);
            cp16(dA + 8192, pAl + so);
            cp16(dB,        pBh + so);
            cp16(dB + 8192, pBl + so);
        }
    };

    // Prologue: 2 stages in flight (3rd buffer free for the first prefetch).
    load_stage(0, 0); CP_COMMIT();
    load_stage(1, 1); CP_COMMIT();

    float acc[4][4][4];
    #pragma unroll
    for (int i = 0; i < 4; i++)
        #pragma unroll
        for (int j = 0; j < 4; j++)
            #pragma unroll
            for (int q = 0; q < 4; q++) acc[i][j][q] = 0.0f;

    const int lrow8  = lane & 7;
    const int lhalfA = (lane >> 3) & 1;
    const int lkA    = lane >> 4;
    const int lhalfB = lane >> 4;
    const int lkB    = (lane >> 3) & 1;

    for (int kt = 0; kt < KT; kt++) {
        CP_WAIT1();            // stage kt complete (kt+1 may still be in flight)
        __syncthreads();
        if (kt + 2 < KT) load_stage((kt + 2) % 3, kt + 2);  // free 3rd buffer
        CP_COMMIT();

        const uint32_t st = sb + (kt % 3) * STAGE_B;
        #pragma unroll
        for (int ks = 0; ks < 2; ks++) {
            const int kc = ks * 2;
            uint32_t ahf[4][4], alf[4][4];
            #pragma unroll
            for (int i = 0; i < 4; i++) {
                const int row = wm * 64 + i * 16 + lrow8 + lhalfA * 8;
                const uint32_t ad = st + row * 64 +
                    ((((uint32_t)(kc + lkA)) ^ ((row >> 1) & 3)) << 4);
                LDSM_X4(ahf[i][0], ahf[i][1], ahf[i][2], ahf[i][3], ad);
                LDSM_X4(alf[i][0], alf[i][1], alf[i][2], alf[i][3], ad + 8192);
            }
            #pragma unroll
            for (int jp = 0; jp < 2; jp++) {
                const int nrow = wn * 32 + jp * 16 + lrow8 + lhalfB * 8;
                const uint32_t bd = st + 16384 + nrow * 64 +
                    ((((uint32_t)(kc + lkB)) ^ ((nrow >> 1) & 3)) << 4);
                uint32_t bh0, bh1, bh2, bh3, bl0, bl1, bl2, bl3;
                LDSM_X4(bh0, bh1, bh2, bh3, bd);
                LDSM_X4(bl0, bl1, bl2, bl3, bd + 8192);
                #pragma unroll
                for (int i = 0; i < 4; i++) {
                    float* c0 = acc[i][jp * 2];
                    float* c1 = acc[i][jp * 2 + 1];
                    MMA16816(c0, ahf[i][0], ahf[i][1], ahf[i][2], ahf[i][3], bh0, bh1);
                    MMA16816(c0, ahf[i][0], ahf[i][1], ahf[i][2], ahf[i][3], bl0, bl1);
                    MMA16816(c0, alf[i][0], alf[i][1], alf[i][2], alf[i][3], bh0, bh1);
                    MMA16816(c1, ahf[i][0], ahf[i][1], ahf[i][2], ahf[i][3], bh2, bh3);
                    MMA16816(c1, ahf[i][0], ahf[i][1], ahf[i][2], ahf[i][3], bl2, bl3);
                    MMA16816(c1, alf[i][0], alf[i][1], alf[i][2], alf[i][3], bh2, bh3);
                }
            }
        }
    }

    // ---- epilogue -----------------------------------------------------------
    #pragma unroll
    for (int i = 0; i < 4; i++) {
        const size_t r = m0 + wm * 64 + i * 16 + (lane >> 2);
        #pragma unroll
        for (int j = 0; j < 4; j++) {
            const size_t c = n0 + wn * 32 + j * 8 + (lane & 3) * 2;
            *reinterpret_cast<float2*>(C + r * (size_t)Ntot + c) =
                make_float2(acc[i][j][0], acc[i][j][1]);
            *reinterpret_cast<float2*>(C + (r + 8) * (size_t)Ntot + c) =
                make_float2(acc[i][j][2], acc[i][j][3]);
        }
    }
}

// ---------------------------------------------------------------------------
// fp32 -> (hi, lo) bf16 split, elementwise. 8 elements per thread.
// ---------------------------------------------------------------------------
__global__ __launch_bounds__(256) void split_bf16(
    const float* __restrict__ src, __nv_bfloat16* __restrict__ hi,
    __nv_bfloat16* __restrict__ lo, size_t total8)
{
    size_t idx = (size_t)blockIdx.x * blockDim.x + threadIdx.x;
    if (idx >= total8) return;
    const float* s = src + idx * 8;
    float4 v0 = *reinterpret_cast<const float4*>(s);
    float4 v1 = *reinterpret_cast<const float4*>(s + 4);
    float v[8] = {v0.x, v0.y, v0.z, v0.w, v1.x, v1.y, v1.z, v1.w};
    union { __nv_bfloat16 h[8]; uint4 u; } H, L;
    #pragma unroll
    for (int i = 0; i < 8; i++) {
        __nv_bfloat16 h = __float2bfloat16(v[i]);
        H.h[i] = h;
        L.h[i] = __float2bfloat16(v[i] - __bfloat162float(h));
    }
    *reinterpret_cast<uint4*>(hi + idx * 8) = H.u;
    *reinterpret_cast<uint4*>(lo + idx * 8) = L.u;
}

// ---------------------------------------------------------------------------
// Fused gate + causal depthwise conv(K=4) + gate; outputs split bf16 u.
// ---------------------------------------------------------------------------
__global__ __launch_bounds__(256) void conv_gate_split(
    const float* __restrict__ bcx, const float* __restrict__ cw,
    __nv_bfloat16* __restrict__ uh, __nv_bfloat16* __restrict__ ul)
{
    size_t idx = (size_t)blockIdx.x * blockDim.x + threadIdx.x;
    if (idx >= (size_t)MTOK * 256) return;
    const int g = (int)(idx & 255);
    const size_t m = idx >> 8;
    const int d0 = g * 8;
    const int s = (int)(m % SEQ);

    float w[8][4];
    #pragma unroll
    for (int j = 0; j < 8; j++) {
        float4 wv = *reinterpret_cast<const float4*>(cw + (size_t)(d0 + j) * 4);
        w[j][0] = wv.x; w[j][1] = wv.y; w[j][2] = wv.z; w[j][3] = wv.w;
    }

    float acc[8] = {0, 0, 0, 0, 0, 0, 0, 0};
    #pragma unroll
    for (int back = 0; back < 4; back++) {
        if (s - back >= 0) {
            const float* row = bcx + (m - back) * (size_t)N1;
            float4 b0 = *reinterpret_cast<const float4*>(row + d0);
            float4 b1 = *reinterpret_cast<const float4*>(row + d0 + 4);
            float4 x0 = *reinterpret_cast<const float4*>(row + 2 * D_MODEL + d0);
            float4 x1 = *reinterpret_cast<const float4*>(row + 2 * D_MODEL + d0 + 4);
            float bb[8] = {b0.x, b0.y, b0.z, b0.w, b1.x, b1.y, b1.z, b1.w};
            float xx[8] = {x0.x, x0.y, x0.z, x0.w, x1.x, x1.y, x1.z, x1.w};
            #pragma unroll
            for (int j = 0; j < 8; j++)
                acc[j] = fmaf(bb[j] * xx[j], w[j][3 - back], acc[j]);
        }
    }
    const float* crow = bcx + m * (size_t)N1 + D_MODEL;
    float4 c0 = *reinterpret_cast<const float4*>(crow + d0);
    float4 c1 = *reinterpret_cast<const float4*>(crow + d0 + 4);
    float cc[8] = {c0.x, c0.y, c0.z, c0.w, c1.x, c1.y, c1.z, c1.w};

    union { __nv_bfloat16 h[8]; uint4 u; } H, L;
    #pragma unroll
    for (int j = 0; j < 8; j++) {
        float u = cc[j] * acc[j];
        __nv_bfloat16 h = __float2bfloat16(u);
        H.h[j] = h;
        L.h[j] = __float2bfloat16(u - __bfloat162float(h));
    }
    const size_t off = m * (size_t)D_MODEL + d0;
    *reinterpret_cast<uint4*>(uh + off) = H.u;
    *reinterpret_cast<uint4*>(ul + off) = L.u;
}

// ---------------------------------------------------------------------------
extern "C" void kernel_launch(void* const* d_in, const int* in_sizes, int n_in,
                              void* d_out, int out_size)
{
    const float* x  = (const float*)d_in[0];
    const float* w1 = (const float*)d_in[1];
    const float* w2 = (const float*)d_in[2];
    const float* cw = (const float*)d_in[3];
    float* out = (float*)d_out;

    __nv_bfloat16 *xh, *xl, *w1h, *w1l, *w2h, *w2l, *uh, *ul;
    float* bcx;
    cudaGetSymbolAddress((void**)&xh,  g_xh);
    cudaGetSymbolAddress((void**)&xl,  g_xl);
    cudaGetSymbolAddress((void**)&w1h, g_w1h);
    cudaGetSymbolAddress((void**)&w1l, g_w1l);
    cudaGetSymbolAddress((void**)&w2h, g_w2h);
    cudaGetSymbolAddress((void**)&w2l, g_w2l);
    cudaGetSymbolAddress((void**)&uh,  g_uh);
    cudaGetSymbolAddress((void**)&ul,  g_ul);
    cudaGetSymbolAddress((void**)&bcx, g_bcx);

    cudaFuncSetAttribute(gemm_split,
                         cudaFuncAttributeMaxDynamicSharedMemorySize, GEMM_SMEM);

    split_bf16<<<(int)(((size_t)MTOK * KEL / 8 + 255) / 256), 256>>>(
        x, xh, xl, (size_t)MTOK * KEL / 8);
    split_bf16<<<(int)(((size_t)N1 * KEL / 8 + 255) / 256), 256>>>(
        w1, w1h, w1l, (size_t)N1 * KEL / 8);
    split_bf16<<<(int)(((size_t)D_MODEL * KEL / 8 + 255) / 256), 256>>>(
        w2, w2h, w2l, (size_t)D_MODEL * KEL / 8);

    // GEMM1: bcx = x @ w1^T
    {
        dim3 grid(N1 / 128, MTOK / 128);
        gemm_split<<<grid, 256, GEMM_SMEM>>>(xh, xl, w1h, w1l, bcx, N1);
    }

    conv_gate_split<<<MTOK * 256 / 256, 256>>>(bcx, cw, uh, ul);

    // GEMM2: out = u @ w2^T
    {
        dim3 grid(D_MODEL / 128, MTOK / 128);
        gemm_split<<<grid, 256, GEMM_SMEM>>>(uh, ul, w2h, w2l, out, D_MODEL);
    }
}

// round 9
// speedup vs baseline: 1.1750x; 1.0711x over previous
#include <cuda_runtime.h>
#include <cuda_bf16.h>
#include <cstdint>

// ---------------------------------------------------------------------------
// GatedShortBlock via split-bf16 HMMA (mma.sync):
//   bcx = x @ w1^T   (16384 x 6144, K=2048)
//   u   = Cg * causal_conv4(Bg * Xg)
//   out = u @ w2^T   (16384 x 2048, K=2048)
// C = Ah*Bh^T + Ah*Bl^T + Al*Bh^T  (bf16 operands, fp32 accum, err ~2^-17)
// R9: R8 (128x128, 2 CTAs/SM, fixed 3-stage pipe) +
//     (a) LDSM/MMA interleave: B+A[0] first, A[i+1] hidden under MMAs of A[i]
//     (b) prefetch issue moved between kc=0 and kc=1 (hides cp.async burst)
// ---------------------------------------------------------------------------

#define D_MODEL 2048
#define SEQ     4096
#define MTOK    16384
#define N1      6144
#define KEL     2048
#define KT      64            // 2048 / 32 k-slabs
#define KSZ     4

// ---------------- scratch ----------------------------------------------------
__device__ __align__(16) __nv_bfloat16 g_xh [(size_t)MTOK * KEL];
__device__ __align__(16) __nv_bfloat16 g_xl [(size_t)MTOK * KEL];
__device__ __align__(16) __nv_bfloat16 g_w1h[(size_t)N1 * KEL];
__device__ __align__(16) __nv_bfloat16 g_w1l[(size_t)N1 * KEL];
__device__ __align__(16) __nv_bfloat16 g_w2h[(size_t)D_MODEL * KEL];
__device__ __align__(16) __nv_bfloat16 g_w2l[(size_t)D_MODEL * KEL];
__device__ __align__(16) __nv_bfloat16 g_uh [(size_t)MTOK * KEL];
__device__ __align__(16) __nv_bfloat16 g_ul [(size_t)MTOK * KEL];
__device__ float g_bcx[(size_t)MTOK * N1];

// ---------------- asm helpers ------------------------------------------------
__device__ __forceinline__ uint32_t smem_u32(const void* p) {
    uint32_t a;
    asm("{ .reg .u64 t; cvta.to.shared.u64 t, %1; cvt.u32.u64 %0, t; }" : "=r"(a) : "l"(p));
    return a;
}
__device__ __forceinline__ void cp16(uint32_t dst, const void* src) {
    asm volatile("cp.async.cg.shared.global [%0], [%1], 16;" :: "r"(dst), "l"(src));
}
#define CP_COMMIT() asm volatile("cp.async.commit_group;" ::: "memory")
#define CP_WAIT1()  asm volatile("cp.async.wait_group 1;" ::: "memory")

#define LDSM_X4(r0, r1, r2, r3, addr) \
    asm volatile("ldmatrix.sync.aligned.m8n8.x4.shared.b16 {%0,%1,%2,%3}, [%4];" \
        : "=r"(r0), "=r"(r1), "=r"(r2), "=r"(r3) : "r"(addr))

#define MMA16816(c, a0, a1, a2, a3, b0, b1) \
    asm volatile("mma.sync.aligned.m16n8k16.row.col.f32.bf16.bf16.f32 " \
        "{%0,%1,%2,%3}, {%4,%5,%6,%7}, {%8,%9}, {%0,%1,%2,%3};" \
        : "+f"((c)[0]), "+f"((c)[1]), "+f"((c)[2]), "+f"((c)[3]) \
        : "r"(a0), "r"(a1), "r"(a2), "r"(a3), "r"(b0), "r"(b1))

// ---------------------------------------------------------------------------
// GEMM kernel. CTA tile 128x128, 256 threads, warp grid 2(m) x 4(n),
// warp tile 64x32. Smem per stage (32KB): [Ah 8K | Al 8K | Bh 8K | Bl 8K],
// rows are 64B (32 K-elems), 16B chunks XOR-swizzled by ((row>>1)&3).
// 3 stages = 96KB -> 2 CTAs/SM.
// ---------------------------------------------------------------------------
#define STAGE_B   32768
#define GEMM_SMEM (3 * STAGE_B)   // 98304

__global__ __launch_bounds__(256, 2) void gemm_split(
    const __nv_bfloat16* __restrict__ Ah, const __nv_bfloat16* __restrict__ Al,
    const __nv_bfloat16* __restrict__ Bh, const __nv_bfloat16* __restrict__ Bl,
    float* __restrict__ C, int Ntot)
{
    extern __shared__ __align__(1024) char smem[];
    const uint32_t sb = smem_u32(smem);
    const int tid  = threadIdx.x;
    const int lane = tid & 31;
    const int wid  = tid >> 5;
    const int wm   = wid >> 2;        // 0..1  (m)
    const int wn   = wid & 3;         // 0..3  (n)

    const size_t m0 = (size_t)blockIdx.y * 128;
    const size_t n0 = (size_t)blockIdx.x * 128;

    const char* pAh = (const char*)(Ah + m0 * (size_t)KEL);
    const char* pAl = (const char*)(Al + m0 * (size_t)KEL);
    const char* pBh = (const char*)(Bh + n0 * (size_t)KEL);
    const char* pBl = (const char*)(Bl + n0 * (size_t)KEL);

    auto load_stage = [&](int s, int kt) {
        const uint32_t st = sb + s * STAGE_B;
        const size_t kb = (size_t)kt * 64;   // byte offset along K
        #pragma unroll
        for (int rep = 0; rep < 2; rep++) {   // 128 rows x 4 chunks = 512 slots
            const int idx = rep * 256 + tid;
            const int row = idx >> 2, c = idx & 3;
            const uint32_t sw = ((((uint32_t)c) ^ ((row >> 1) & 3)) << 4);
            const uint32_t dA = st + row * 64 + sw;
            const uint32_t dB = st + 16384 + row * 64 + sw;
            const size_t so = (size_t)row * (KEL * 2) + kb + c * 16;
            cp16(dA,        pAh + so);
            cp16(dA + 8192, pAl + so);
            cp16(dB,        pBh + so);
            cp16(dB + 8192, pBl + so);
        }
    };

    // Prologue: 2 stages in flight (3rd buffer free for the first prefetch).
    load_stage(0, 0); CP_COMMIT();
    load_stage(1, 1); CP_COMMIT();

    float acc[4][4][4];
    #pragma unroll
    for (int i = 0; i < 4; i++)
        #pragma unroll
        for (int j = 0; j < 4; j++)
            #pragma unroll
            for (int q = 0; q < 4; q++) acc[i][j][q] = 0.0f;

    const int lrow8  = lane & 7;
    const int lhalfA = (lane >> 3) & 1;
    const int lkA    = lane >> 4;
    const int lhalfB = lane >> 4;
    const int lkB    = (lane >> 3) & 1;

    for (int kt = 0; kt < KT; kt++) {
        CP_WAIT1();            // stage kt complete (kt+1 may still be in flight)
        __syncthreads();

        const uint32_t st = sb + (kt % 3) * STAGE_B;
        #pragma unroll
        for (int ks = 0; ks < 2; ks++) {
            const int kc = ks * 2;

            // ---- B fragments for both jp first (MMAs for i=0 need them) ----
            uint32_t bh[4][2], bl[4][2];
            #pragma unroll
            for (int jp = 0; jp < 2; jp++) {
                const int nrow = wn * 32 + jp * 16 + lrow8 + lhalfB * 8;
                const uint32_t bd = st + 16384 + nrow * 64 +
                    ((((uint32_t)(kc + lkB)) ^ ((nrow >> 1) & 3)) << 4);
                LDSM_X4(bh[jp*2][0], bh[jp*2][1], bh[jp*2+1][0], bh[jp*2+1][1], bd);
                LDSM_X4(bl[jp*2][0], bl[jp*2][1], bl[jp*2+1][0], bl[jp*2+1][1], bd + 8192);
            }
            // ---- A[0], then interleave A[i+1] under MMAs of A[i] ----
            uint32_t ahf[4][4], alf[4][4];
            {
                const int row = wm * 64 + 0 * 16 + lrow8 + lhalfA * 8;
                const uint32_t ad = st + row * 64 +
                    ((((uint32_t)(kc + lkA)) ^ ((row >> 1) & 3)) << 4);
                LDSM_X4(ahf[0][0], ahf[0][1], ahf[0][2], ahf[0][3], ad);
                LDSM_X4(alf[0][0], alf[0][1], alf[0][2], alf[0][3], ad + 8192);
            }
            #pragma unroll
            for (int i = 0; i < 4; i++) {
                if (i < 3) {
                    const int row = wm * 64 + (i + 1) * 16 + lrow8 + lhalfA * 8;
                    const uint32_t ad = st + row * 64 +
                        ((((uint32_t)(kc + lkA)) ^ ((row >> 1) & 3)) << 4);
                    LDSM_X4(ahf[i+1][0], ahf[i+1][1], ahf[i+1][2], ahf[i+1][3], ad);
                    LDSM_X4(alf[i+1][0], alf[i+1][1], alf[i+1][2], alf[i+1][3], ad + 8192);
                }
                #pragma unroll
                for (int jp = 0; jp < 2; jp++) {
                    float* c0 = acc[i][jp * 2];
                    float* c1 = acc[i][jp * 2 + 1];
                    MMA16816(c0, ahf[i][0], ahf[i][1], ahf[i][2], ahf[i][3], bh[jp*2][0], bh[jp*2][1]);
                    MMA16816(c0, ahf[i][0], ahf[i][1], ahf[i][2], ahf[i][3], bl[jp*2][0], bl[jp*2][1]);
                    MMA16816(c0, alf[i][0], alf[i][1], alf[i][2], alf[i][3], bh[jp*2][0], bh[jp*2][1]);
                    MMA16816(c1, ahf[i][0], ahf[i][1], ahf[i][2], ahf[i][3], bh[jp*2+1][0], bh[jp*2+1][1]);
                    MMA16816(c1, ahf[i][0], ahf[i][1], ahf[i][2], ahf[i][3], bl[jp*2+1][0], bl[jp*2+1][1]);
                    MMA16816(c1, alf[i][0], alf[i][1], alf[i][2], alf[i][3], bh[jp*2+1][0], bh[jp*2+1][1]);
                }
            }

            // ---- prefetch issued between kc=0 and kc=1, hidden under MMAs ----
            if (ks == 0) {
                if (kt + 2 < KT) load_stage((kt + 2) % 3, kt + 2);
                CP_COMMIT();
            }
        }
    }

    // ---- epilogue -----------------------------------------------------------
    #pragma unroll
    for (int i = 0; i < 4; i++) {
        const size_t r = m0 + wm * 64 + i * 16 + (lane >> 2);
        #pragma unroll
        for (int j = 0; j < 4; j++) {
            const size_t c = n0 + wn * 32 + j * 8 + (lane & 3) * 2;
            *reinterpret_cast<float2*>(C + r * (size_t)Ntot + c) =
                make_float2(acc[i][j][0], acc[i][j][1]);
            *reinterpret_cast<float2*>(C + (r + 8) * (size_t)Ntot + c) =
                make_float2(acc[i][j][2], acc[i][j][3]);
        }
    }
}

// ---------------------------------------------------------------------------
// fp32 -> (hi, lo) bf16 split, elementwise. 8 elements per thread.
// ---------------------------------------------------------------------------
__global__ __launch_bounds__(256) void split_bf16(
    const float* __restrict__ src, __nv_bfloat16* __restrict__ hi,
    __nv_bfloat16* __restrict__ lo, size_t total8)
{
    size_t idx = (size_t)blockIdx.x * blockDim.x + threadIdx.x;
    if (idx >= total8) return;
    const float* s = src + idx * 8;
    float4 v0 = *reinterpret_cast<const float4*>(s);
    float4 v1 = *reinterpret_cast<const float4*>(s + 4);
    float v[8] = {v0.x, v0.y, v0.z, v0.w, v1.x, v1.y, v1.z, v1.w};
    union { __nv_bfloat16 h[8]; uint4 u; } H, L;
    #pragma unroll
    for (int i = 0; i < 8; i++) {
        __nv_bfloat16 h = __float2bfloat16(v[i]);
        H.h[i] = h;
        L.h[i] = __float2bfloat16(v[i] - __bfloat162float(h));
    }
    *reinterpret_cast<uint4*>(hi + idx * 8) = H.u;
    *reinterpret_cast<uint4*>(lo + idx * 8) = L.u;
}

// ---------------------------------------------------------------------------
// Fused gate + causal depthwise conv(K=4) + gate; outputs split bf16 u.
// ---------------------------------------------------------------------------
__global__ __launch_bounds__(256) void conv_gate_split(
    const float* __restrict__ bcx, const float* __restrict__ cw,
    __nv_bfloat16* __restrict__ uh, __nv_bfloat16* __restrict__ ul)
{
    size_t idx = (size_t)blockIdx.x * blockDim.x + threadIdx.x;
    if (idx >= (size_t)MTOK * 256) return;
    const int g = (int)(idx & 255);
    const size_t m = idx >> 8;
    const int d0 = g * 8;
    const int s = (int)(m % SEQ);

    float w[8][4];
    #pragma unroll
    for (int j = 0; j < 8; j++) {
        float4 wv = *reinterpret_cast<const float4*>(cw + (size_t)(d0 + j) * 4);
        w[j][0] = wv.x; w[j][1] = wv.y; w[j][2] = wv.z; w[j][3] = wv.w;
    }

    float acc[8] = {0, 0, 0, 0, 0, 0, 0, 0};
    #pragma unroll
    for (int back = 0; back < 4; back++) {
        if (s - back >= 0) {
            const float* row = bcx + (m - back) * (size_t)N1;
            float4 b0 = *reinterpret_cast<const float4*>(row + d0);
            float4 b1 = *reinterpret_cast<const float4*>(row + d0 + 4);
            float4 x0 = *reinterpret_cast<const float4*>(row + 2 * D_MODEL + d0);
            float4 x1 = *reinterpret_cast<const float4*>(row + 2 * D_MODEL + d0 + 4);
            float bb[8] = {b0.x, b0.y, b0.z, b0.w, b1.x, b1.y, b1.z, b1.w};
            float xx[8] = {x0.x, x0.y, x0.z, x0.w, x1.x, x1.y, x1.z, x1.w};
            #pragma unroll
            for (int j = 0; j < 8; j++)
                acc[j] = fmaf(bb[j] * xx[j], w[j][3 - back], acc[j]);
        }
    }
    const float* crow = bcx + m * (size_t)N1 + D_MODEL;
    float4 c0 = *reinterpret_cast<const float4*>(crow + d0);
    float4 c1 = *reinterpret_cast<const float4*>(crow + d0 + 4);
    float cc[8] = {c0.x, c0.y, c0.z, c0.w, c1.x, c1.y, c1.z, c1.w};

    union { __nv_bfloat16 h[8]; uint4 u; } H, L;
    #pragma unroll
    for (int j = 0; j < 8; j++) {
        float u = cc[j] * acc[j];
        __nv_bfloat16 h = __float2bfloat16(u);
        H.h[j] = h;
        L.h[j] = __float2bfloat16(u - __bfloat162float(h));
    }
    const size_t off = m * (size_t)D_MODEL + d0;
    *reinterpret_cast<uint4*>(uh + off) = H.u;
    *reinterpret_cast<uint4*>(ul + off) = L.u;
}

// ---------------------------------------------------------------------------
extern "C" void kernel_launch(void* const* d_in, const int* in_sizes, int n_in,
                              void* d_out, int out_size)
{
    const float* x  = (const float*)d_in[0];
    const float* w1 = (const float*)d_in[1];
    const float* w2 = (const float*)d_in[2];
    const float* cw = (const float*)d_in[3];
    float* out = (float*)d_out;

    __nv_bfloat16 *xh, *xl, *w1h, *w1l, *w2h, *w2l, *uh, *ul;
    float* bcx;
    cudaGetSymbolAddress((void**)&xh,  g_xh);
    cudaGetSymbolAddress((void**)&xl,  g_xl);
    cudaGetSymbolAddress((void**)&w1h, g_w1h);
    cudaGetSymbolAddress((void**)&w1l, g_w1l);
    cudaGetSymbolAddress((void**)&w2h, g_w2h);
    cudaGetSymbolAddress((void**)&w2l, g_w2l);
    cudaGetSymbolAddress((void**)&uh,  g_uh);
    cudaGetSymbolAddress((void**)&ul,  g_ul);
    cudaGetSymbolAddress((void**)&bcx, g_bcx);

    cudaFuncSetAttribute(gemm_split,
                         cudaFuncAttributeMaxDynamicSharedMemorySize, GEMM_SMEM);

    split_bf16<<<(int)(((size_t)MTOK * KEL / 8 + 255) / 256), 256>>>(
        x, xh, xl, (size_t)MTOK * KEL / 8);
    split_bf16<<<(int)(((size_t)N1 * KEL / 8 + 255) / 256), 256>>>(
        w1, w1h, w1l, (size_t)N1 * KEL / 8);
    split_bf16<<<(int)(((size_t)D_MODEL * KEL / 8 + 255) / 256), 256>>>(
        w2, w2h, w2l, (size_t)D_MODEL * KEL / 8);

    // GEMM1: bcx = x @ w1^T
    {
        dim3 grid(N1 / 128, MTOK / 128);
        gemm_split<<<grid, 256, GEMM_SMEM>>>(xh, xl, w1h, w1l, bcx, N1);
    }

    conv_gate_split<<<MTOK * 256 / 256, 256>>>(bcx, cw, uh, ul);

    // GEMM2: out = u @ w2^T
    {
        dim3 grid(D_MODEL / 128, MTOK / 128);
        gemm_split<<<grid, 256, GEMM_SMEM>>>(uh, ul, w2h, w2l, out, D_MODEL);
    }
}

// round 10
// speedup vs baseline: 1.2134x; 1.0326x over previous
#include <cuda_runtime.h>
#include <cuda_bf16.h>
#include <cstdint>

// ---------------------------------------------------------------------------
// GatedShortBlock via split-bf16 HMMA (mma.sync):
//   bcx = x @ w1^T   (16384 x 6144, K=2048)
//   u   = Cg * causal_conv4(Bg * Xg)
//   out = u @ w2^T   (16384 x 2048, K=2048)
// C = Ah*Bh^T + Ah*Bl^T + Al*Bh^T  (bf16 operands, fp32 accum, err ~2^-17)
// R10: GEMM = R9 (85% tensor, smem-crossbar plateau). New conv_gate:
//      register-rolling strips (8 d-cols x 64 tokens/thread), 3 reads/elem
//      instead of 9 (taps held in a 4-slot register ring).
// ---------------------------------------------------------------------------

#define D_MODEL 2048
#define SEQ     4096
#define MTOK    16384
#define N1      6144
#define KEL     2048
#define KT      64            // 2048 / 32 k-slabs
#define KSZ     4

// ---------------- scratch ----------------------------------------------------
__device__ __align__(16) __nv_bfloat16 g_xh [(size_t)MTOK * KEL];
__device__ __align__(16) __nv_bfloat16 g_xl [(size_t)MTOK * KEL];
__device__ __align__(16) __nv_bfloat16 g_w1h[(size_t)N1 * KEL];
__device__ __align__(16) __nv_bfloat16 g_w1l[(size_t)N1 * KEL];
__device__ __align__(16) __nv_bfloat16 g_w2h[(size_t)D_MODEL * KEL];
__device__ __align__(16) __nv_bfloat16 g_w2l[(size_t)D_MODEL * KEL];
__device__ __align__(16) __nv_bfloat16 g_uh [(size_t)MTOK * KEL];
__device__ __align__(16) __nv_bfloat16 g_ul [(size_t)MTOK * KEL];
__device__ float g_bcx[(size_t)MTOK * N1];

// ---------------- asm helpers ------------------------------------------------
__device__ __forceinline__ uint32_t smem_u32(const void* p) {
    uint32_t a;
    asm("{ .reg .u64 t; cvta.to.shared.u64 t, %1; cvt.u32.u64 %0, t; }" : "=r"(a) : "l"(p));
    return a;
}
__device__ __forceinline__ void cp16(uint32_t dst, const void* src) {
    asm volatile("cp.async.cg.shared.global [%0], [%1], 16;" :: "r"(dst), "l"(src));
}
#define CP_COMMIT() asm volatile("cp.async.commit_group;" ::: "memory")
#define CP_WAIT1()  asm volatile("cp.async.wait_group 1;" ::: "memory")

#define LDSM_X4(r0, r1, r2, r3, addr) \
    asm volatile("ldmatrix.sync.aligned.m8n8.x4.shared.b16 {%0,%1,%2,%3}, [%4];" \
        : "=r"(r0), "=r"(r1), "=r"(r2), "=r"(r3) : "r"(addr))

#define MMA16816(c, a0, a1, a2, a3, b0, b1) \
    asm volatile("mma.sync.aligned.m16n8k16.row.col.f32.bf16.bf16.f32 " \
        "{%0,%1,%2,%3}, {%4,%5,%6,%7}, {%8,%9}, {%0,%1,%2,%3};" \
        : "+f"((c)[0]), "+f"((c)[1]), "+f"((c)[2]), "+f"((c)[3]) \
        : "r"(a0), "r"(a1), "r"(a2), "r"(a3), "r"(b0), "r"(b1))

// ---------------------------------------------------------------------------
// GEMM kernel (unchanged from R9). CTA tile 128x128, 256 threads,
// warp grid 2(m) x 4(n), warp tile 64x32. 3 stages x 32KB -> 2 CTAs/SM.
// ---------------------------------------------------------------------------
#define STAGE_B   32768
#define GEMM_SMEM (3 * STAGE_B)   // 98304

__global__ __launch_bounds__(256, 2) void gemm_split(
    const __nv_bfloat16* __restrict__ Ah, const __nv_bfloat16* __restrict__ Al,
    const __nv_bfloat16* __restrict__ Bh, const __nv_bfloat16* __restrict__ Bl,
    float* __restrict__ C, int Ntot)
{
    extern __shared__ __align__(1024) char smem[];
    const uint32_t sb = smem_u32(smem);
    const int tid  = threadIdx.x;
    const int lane = tid & 31;
    const int wid  = tid >> 5;
    const int wm   = wid >> 2;        // 0..1  (m)
    const int wn   = wid & 3;         // 0..3  (n)

    const size_t m0 = (size_t)blockIdx.y * 128;
    const size_t n0 = (size_t)blockIdx.x * 128;

    const char* pAh = (const char*)(Ah + m0 * (size_t)KEL);
    const char* pAl = (const char*)(Al + m0 * (size_t)KEL);
    const char* pBh = (const char*)(Bh + n0 * (size_t)KEL);
    const char* pBl = (const char*)(Bl + n0 * (size_t)KEL);

    auto load_stage = [&](int s, int kt) {
        const uint32_t st = sb + s * STAGE_B;
        const size_t kb = (size_t)kt * 64;   // byte offset along K
        #pragma unroll
        for (int rep = 0; rep < 2; rep++) {   // 128 rows x 4 chunks = 512 slots
            const int idx = rep * 256 + tid;
            const int row = idx >> 2, c = idx & 3;
            const uint32_t sw = ((((uint32_t)c) ^ ((row >> 1) & 3)) << 4);
            const uint32_t dA = st + row * 64 + sw;
            const uint32_t dB = st + 16384 + row * 64 + sw;
            const size_t so = (size_t)row * (KEL * 2) + kb + c * 16;
            cp16(dA,        pAh + so);
            cp16(dA + 8192, pAl + so);
            cp16(dB,        pBh + so);
            cp16(dB + 8192, pBl + so);
        }
    };

    // Prologue: 2 stages in flight (3rd buffer free for the first prefetch).
    load_stage(0, 0); CP_COMMIT();
    load_stage(1, 1); CP_COMMIT();

    float acc[4][4][4];
    #pragma unroll
    for (int i = 0; i < 4; i++)
        #pragma unroll
        for (int j = 0; j < 4; j++)
            #pragma unroll
            for (int q = 0; q < 4; q++) acc[i][j][q] = 0.0f;

    const int lrow8  = lane & 7;
    const int lhalfA = (lane >> 3) & 1;
    const int lkA    = lane >> 4;
    const int lhalfB = lane >> 4;
    const int lkB    = (lane >> 3) & 1;

    for (int kt = 0; kt < KT; kt++) {
        CP_WAIT1();            // stage kt complete (kt+1 may still be in flight)
        __syncthreads();

        const uint32_t st = sb + (kt % 3) * STAGE_B;
        #pragma unroll
        for (int ks = 0; ks < 2; ks++) {
            const int kc = ks * 2;

            // ---- B fragments for both jp first (MMAs for i=0 need them) ----
            uint32_t bh[4][2], bl[4][2];
            #pragma unroll
            for (int jp = 0; jp < 2; jp++) {
                const int nrow = wn * 32 + jp * 16 + lrow8 + lhalfB * 8;
                const uint32_t bd = st + 16384 + nrow * 64 +
                    ((((uint32_t)(kc + lkB)) ^ ((nrow >> 1) & 3)) << 4);
                LDSM_X4(bh[jp*2][0], bh[jp*2][1], bh[jp*2+1][0], bh[jp*2+1][1], bd);
                LDSM_X4(bl[jp*2][0], bl[jp*2][1], bl[jp*2+1][0], bl[jp*2+1][1], bd + 8192);
            }
            // ---- A[0], then interleave A[i+1] under MMAs of A[i] ----
            uint32_t ahf[4][4], alf[4][4];
            {
                const int row = wm * 64 + 0 * 16 + lrow8 + lhalfA * 8;
                const uint32_t ad = st + row * 64 +
                    ((((uint32_t)(kc + lkA)) ^ ((row >> 1) & 3)) << 4);
                LDSM_X4(ahf[0][0], ahf[0][1], ahf[0][2], ahf[0][3], ad);
                LDSM_X4(alf[0][0], alf[0][1], alf[0][2], alf[0][3], ad + 8192);
            }
            #pragma unroll
            for (int i = 0; i < 4; i++) {
                if (i < 3) {
                    const int row = wm * 64 + (i + 1) * 16 + lrow8 + lhalfA * 8;
                    const uint32_t ad = st + row * 64 +
                        ((((uint32_t)(kc + lkA)) ^ ((row >> 1) & 3)) << 4);
                    LDSM_X4(ahf[i+1][0], ahf[i+1][1], ahf[i+1][2], ahf[i+1][3], ad);
                    LDSM_X4(alf[i+1][0], alf[i+1][1], alf[i+1][2], alf[i+1][3], ad + 8192);
                }
                #pragma unroll
                for (int jp = 0; jp < 2; jp++) {
                    float* c0 = acc[i][jp * 2];
                    float* c1 = acc[i][jp * 2 + 1];
                    MMA16816(c0, ahf[i][0], ahf[i][1], ahf[i][2], ahf[i][3], bh[jp*2][0], bh[jp*2][1]);
                    MMA16816(c0, ahf[i][0], ahf[i][1], ahf[i][2], ahf[i][3], bl[jp*2][0], bl[jp*2][1]);
                    MMA16816(c0, alf[i][0], alf[i][1], alf[i][2], alf[i][3], bh[jp*2][0], bh[jp*2][1]);
                    MMA16816(c1, ahf[i][0], ahf[i][1], ahf[i][2], ahf[i][3], bh[jp*2+1][0], bh[jp*2+1][1]);
                    MMA16816(c1, ahf[i][0], ahf[i][1], ahf[i][2], ahf[i][3], bl[jp*2+1][0], bl[jp*2+1][1]);
                    MMA16816(c1, alf[i][0], alf[i][1], alf[i][2], alf[i][3], bh[jp*2+1][0], bh[jp*2+1][1]);
                }
            }

            // ---- prefetch issued between kc=0 and kc=1, hidden under MMAs ----
            if (ks == 0) {
                if (kt + 2 < KT) load_stage((kt + 2) % 3, kt + 2);
                CP_COMMIT();
            }
        }
    }

    // ---- epilogue -----------------------------------------------------------
    #pragma unroll
    for (int i = 0; i < 4; i++) {
        const size_t r = m0 + wm * 64 + i * 16 + (lane >> 2);
        #pragma unroll
        for (int j = 0; j < 4; j++) {
            const size_t c = n0 + wn * 32 + j * 8 + (lane & 3) * 2;
            *reinterpret_cast<float2*>(C + r * (size_t)Ntot + c) =
                make_float2(acc[i][j][0], acc[i][j][1]);
            *reinterpret_cast<float2*>(C + (r + 8) * (size_t)Ntot + c) =
                make_float2(acc[i][j][2], acc[i][j][3]);
        }
    }
}

// ---------------------------------------------------------------------------
// fp32 -> (hi, lo) bf16 split, elementwise. 8 elements per thread.
// ---------------------------------------------------------------------------
__global__ __launch_bounds__(256) void split_bf16(
    const float* __restrict__ src, __nv_bfloat16* __restrict__ hi,
    __nv_bfloat16* __restrict__ lo, size_t total8)
{
    size_t idx = (size_t)blockIdx.x * blockDim.x + threadIdx.x;
    if (idx >= total8) return;
    const float* s = src + idx * 8;
    float4 v0 = *reinterpret_cast<const float4*>(s);
    float4 v1 = *reinterpret_cast<const float4*>(s + 4);
    float v[8] = {v0.x, v0.y, v0.z, v0.w, v1.x, v1.y, v1.z, v1.w};
    union { __nv_bfloat16 h[8]; uint4 u; } H, L;
    #pragma unroll
    for (int i = 0; i < 8; i++) {
        __nv_bfloat16 h = __float2bfloat16(v[i]);
        H.h[i] = h;
        L.h[i] = __float2bfloat16(v[i] - __bfloat162float(h));
    }
    *reinterpret_cast<uint4*>(hi + idx * 8) = H.u;
    *reinterpret_cast<uint4*>(lo + idx * 8) = L.u;
}

// ---------------------------------------------------------------------------
// Fused gate + causal depthwise conv(K=4) + gate; outputs split bf16 u.
// Register-rolling: each thread owns 8 d-cols x 64 consecutive tokens,
// keeps last 3 gated vectors in a 4-slot register ring -> 3 reads/element.
// Strips never cross sequence boundaries (4096 % 64 == 0).
// ---------------------------------------------------------------------------
#define STRIP 64

__global__ __launch_bounds__(256) void conv_gate_roll(
    const float* __restrict__ bcx, const float* __restrict__ cw,
    __nv_bfloat16* __restrict__ uh, __nv_bfloat16* __restrict__ ul)
{
    const int t = blockIdx.x * blockDim.x + threadIdx.x;
    if (t >= (MTOK / STRIP) * 256) return;
    const int dg    = t & 255;          // d-group (8 cols)
    const int strip = t >> 8;
    const int d0 = dg * 8;
    const size_t m0 = (size_t)strip * STRIP;
    const int s0 = (int)(m0 % SEQ);     // within-sequence start

    float w[8][4];
    #pragma unroll
    for (int j = 0; j < 8; j++) {
        float4 wv = *reinterpret_cast<const float4*>(cw + (size_t)(d0 + j) * 4);
        w[j][0] = wv.x; w[j][1] = wv.y; w[j][2] = wv.z; w[j][3] = wv.w;
    }

    // ring slots: g[(tt + q) & 3] holds gated[m0 + tt - 3 + q] for q=0..2,
    // slot (tt+3)&3 receives the current token.
    float g[4][8];
    #pragma unroll
    for (int q = 0; q < 3; q++) {
        #pragma unroll
        for (int j = 0; j < 8; j++) g[q][j] = 0.0f;
        if (s0 > 0) {   // preload gated[m0-3+q]
            const float* row = bcx + (m0 - 3 + q) * (size_t)N1;
            float4 b0 = *reinterpret_cast<const float4*>(row + d0);
            float4 b1 = *reinterpret_cast<const float4*>(row + d0 + 4);
            float4 x0 = *reinterpret_cast<const float4*>(row + 2 * D_MODEL + d0);
            float4 x1 = *reinterpret_cast<const float4*>(row + 2 * D_MODEL + d0 + 4);
            float bb[8] = {b0.x, b0.y, b0.z, b0.w, b1.x, b1.y, b1.z, b1.w};
            float xx[8] = {x0.x, x0.y, x0.z, x0.w, x1.x, x1.y, x1.z, x1.w};
            #pragma unroll
            for (int j = 0; j < 8; j++) g[q][j] = bb[j] * xx[j];
        }
    }

    #pragma unroll 4
    for (int tt = 0; tt < STRIP; tt++) {
        const size_t m = m0 + tt;
        const float* row = bcx + m * (size_t)N1;
        float4 b0 = *reinterpret_cast<const float4*>(row + d0);
        float4 b1 = *reinterpret_cast<const float4*>(row + d0 + 4);
        float4 x0 = *reinterpret_cast<const float4*>(row + 2 * D_MODEL + d0);
        float4 x1 = *reinterpret_cast<const float4*>(row + 2 * D_MODEL + d0 + 4);
        float bb[8] = {b0.x, b0.y, b0.z, b0.w, b1.x, b1.y, b1.z, b1.w};
        float xx[8] = {x0.x, x0.y, x0.z, x0.w, x1.x, x1.y, x1.z, x1.w};
        float* gc = g[(tt + 3) & 3];
        #pragma unroll
        for (int j = 0; j < 8; j++) gc[j] = bb[j] * xx[j];

        const float* g3 = g[tt & 3];        // token m-3
        const float* g2 = g[(tt + 1) & 3];  // token m-2
        const float* g1 = g[(tt + 2) & 3];  // token m-1

        float4 c0 = *reinterpret_cast<const float4*>(row + D_MODEL + d0);
        float4 c1 = *reinterpret_cast<const float4*>(row + D_MODEL + d0 + 4);
        float cc[8] = {c0.x, c0.y, c0.z, c0.w, c1.x, c1.y, c1.z, c1.w};

        union { __nv_bfloat16 h[8]; uint4 u; } H, L;
        #pragma unroll
        for (int j = 0; j < 8; j++) {
            float a = g3[j] * w[j][0];
            a = fmaf(g2[j], w[j][1], a);
            a = fmaf(g1[j], w[j][2], a);
            a = fmaf(gc[j], w[j][3], a);
            float u = cc[j] * a;
            __nv_bfloat16 h = __float2bfloat16(u);
            H.h[j] = h;
            L.h[j] = __float2bfloat16(u - __bfloat162float(h));
        }
        const size_t off = m * (size_t)D_MODEL + d0;
        *reinterpret_cast<uint4*>(uh + off) = H.u;
        *reinterpret_cast<uint4*>(ul + off) = L.u;
    }
}

// ---------------------------------------------------------------------------
extern "C" void kernel_launch(void* const* d_in, const int* in_sizes, int n_in,
                              void* d_out, int out_size)
{
    const float* x  = (const float*)d_in[0];
    const float* w1 = (const float*)d_in[1];
    const float* w2 = (const float*)d_in[2];
    const float* cw = (const float*)d_in[3];
    float* out = (float*)d_out;

    __nv_bfloat16 *xh, *xl, *w1h, *w1l, *w2h, *w2l, *uh, *ul;
    float* bcx;
    cudaGetSymbolAddress((void**)&xh,  g_xh);
    cudaGetSymbolAddress((void**)&xl,  g_xl);
    cudaGetSymbolAddress((void**)&w1h, g_w1h);
    cudaGetSymbolAddress((void**)&w1l, g_w1l);
    cudaGetSymbolAddress((void**)&w2h, g_w2h);
    cudaGetSymbolAddress((void**)&w2l, g_w2l);
    cudaGetSymbolAddress((void**)&uh,  g_uh);
    cudaGetSymbolAddress((void**)&ul,  g_ul);
    cudaGetSymbolAddress((void**)&bcx, g_bcx);

    cudaFuncSetAttribute(gemm_split,
                         cudaFuncAttributeMaxDynamicSharedMemorySize, GEMM_SMEM);

    split_bf16<<<(int)(((size_t)MTOK * KEL / 8 + 255) / 256), 256>>>(
        x, xh, xl, (size_t)MTOK * KEL / 8);
    split_bf16<<<(int)(((size_t)N1 * KEL / 8 + 255) / 256), 256>>>(
        w1, w1h, w1l, (size_t)N1 * KEL / 8);
    split_bf16<<<(int)(((size_t)D_MODEL * KEL / 8 + 255) / 256), 256>>>(
        w2, w2h, w2l, (size_t)D_MODEL * KEL / 8);

    // GEMM1: bcx = x @ w1^T
    {
        dim3 grid(N1 / 128, MTOK / 128);
        gemm_split<<<grid, 256, GEMM_SMEM>>>(xh, xl, w1h, w1l, bcx, N1);
    }

    // fused gate/conv/gate -> uh, ul (register-rolling strips)
    conv_gate_roll<<<((MTOK / STRIP) * 256) / 256, 256>>>(bcx, cw, uh, ul);

    // GEMM2: out = u @ w2^T
    {
        dim3 grid(D_MODEL / 128, MTOK / 128);
        gemm_split<<<grid, 256, GEMM_SMEM>>>(uh, ul, w2h, w2l, out, D_MODEL);
    }
}

// round 11
// speedup vs baseline: 1.2682x; 1.0452x over previous
#include <cuda_runtime.h>
#include <cuda_bf16.h>
#include <cstdint>

// ---------------------------------------------------------------------------
// GatedShortBlock via split-bf16 HMMA (mma.sync):
//   bcx = x @ w1^T   (16384 x 6144, K=2048)
//   u   = Cg * causal_conv4(Bg * Xg)
//   out = u @ w2^T   (16384 x 2048, K=2048)
// C = Ah*Bh^T + Ah*Bl^T + Al*Bh^T  (bf16 operands, fp32 accum, err ~2^-17)
// R11: R10 + (a) single merged split kernel (3 launches -> 1),
//      (b) LDSM address offsets hoisted out of the k-loop (kt-invariant;
//          kc=1 address = kc=0 address XOR 32).
// ---------------------------------------------------------------------------

#define D_MODEL 2048
#define SEQ     4096
#define MTOK    16384
#define N1      6144
#define KEL     2048
#define KT      64            // 2048 / 32 k-slabs
#define KSZ     4

// ---------------- scratch ----------------------------------------------------
__device__ __align__(16) __nv_bfloat16 g_xh [(size_t)MTOK * KEL];
__device__ __align__(16) __nv_bfloat16 g_xl [(size_t)MTOK * KEL];
__device__ __align__(16) __nv_bfloat16 g_w1h[(size_t)N1 * KEL];
__device__ __align__(16) __nv_bfloat16 g_w1l[(size_t)N1 * KEL];
__device__ __align__(16) __nv_bfloat16 g_w2h[(size_t)D_MODEL * KEL];
__device__ __align__(16) __nv_bfloat16 g_w2l[(size_t)D_MODEL * KEL];
__device__ __align__(16) __nv_bfloat16 g_uh [(size_t)MTOK * KEL];
__device__ __align__(16) __nv_bfloat16 g_ul [(size_t)MTOK * KEL];
__device__ float g_bcx[(size_t)MTOK * N1];

// ---------------- asm helpers ------------------------------------------------
__device__ __forceinline__ uint32_t smem_u32(const void* p) {
    uint32_t a;
    asm("{ .reg .u64 t; cvta.to.shared.u64 t, %1; cvt.u32.u64 %0, t; }" : "=r"(a) : "l"(p));
    return a;
}
__device__ __forceinline__ void cp16(uint32_t dst, const void* src) {
    asm volatile("cp.async.cg.shared.global [%0], [%1], 16;" :: "r"(dst), "l"(src));
}
#define CP_COMMIT() asm volatile("cp.async.commit_group;" ::: "memory")
#define CP_WAIT1()  asm volatile("cp.async.wait_group 1;" ::: "memory")

#define LDSM_X4(r0, r1, r2, r3, addr) \
    asm volatile("ldmatrix.sync.aligned.m8n8.x4.shared.b16 {%0,%1,%2,%3}, [%4];" \
        : "=r"(r0), "=r"(r1), "=r"(r2), "=r"(r3) : "r"(addr))

#define MMA16816(c, a0, a1, a2, a3, b0, b1) \
    asm volatile("mma.sync.aligned.m16n8k16.row.col.f32.bf16.bf16.f32 " \
        "{%0,%1,%2,%3}, {%4,%5,%6,%7}, {%8,%9}, {%0,%1,%2,%3};" \
        : "+f"((c)[0]), "+f"((c)[1]), "+f"((c)[2]), "+f"((c)[3]) \
        : "r"(a0), "r"(a1), "r"(a2), "r"(a3), "r"(b0), "r"(b1))

// ---------------------------------------------------------------------------
// GEMM kernel. CTA tile 128x128, 256 threads, warp grid 2(m) x 4(n),
// warp tile 64x32. Smem per stage (32KB): [Ah 8K | Al 8K | Bh 8K | Bl 8K],
// rows are 64B (32 K-elems), 16B chunks XOR-swizzled by ((row>>1)&3).
// 3 stages = 96KB -> 2 CTAs/SM.
// ---------------------------------------------------------------------------
#define STAGE_B   32768
#define GEMM_SMEM (3 * STAGE_B)   // 98304

__global__ __launch_bounds__(256, 2) void gemm_split(
    const __nv_bfloat16* __restrict__ Ah, const __nv_bfloat16* __restrict__ Al,
    const __nv_bfloat16* __restrict__ Bh, const __nv_bfloat16* __restrict__ Bl,
    float* __restrict__ C, int Ntot)
{
    extern __shared__ __align__(1024) char smem[];
    const uint32_t sb = smem_u32(smem);
    const int tid  = threadIdx.x;
    const int lane = tid & 31;
    const int wid  = tid >> 5;
    const int wm   = wid >> 2;        // 0..1  (m)
    const int wn   = wid & 3;         // 0..3  (n)

    const size_t m0 = (size_t)blockIdx.y * 128;
    const size_t n0 = (size_t)blockIdx.x * 128;

    const char* pAh = (const char*)(Ah + m0 * (size_t)KEL);
    const char* pAl = (const char*)(Al + m0 * (size_t)KEL);
    const char* pBh = (const char*)(Bh + n0 * (size_t)KEL);
    const char* pBl = (const char*)(Bl + n0 * (size_t)KEL);

    auto load_stage = [&](int s, int kt) {
        const uint32_t st = sb + s * STAGE_B;
        const size_t kb = (size_t)kt * 64;   // byte offset along K
        #pragma unroll
        for (int rep = 0; rep < 2; rep++) {   // 128 rows x 4 chunks = 512 slots
            const int idx = rep * 256 + tid;
            const int row = idx >> 2, c = idx & 3;
            const uint32_t sw = ((((uint32_t)c) ^ ((row >> 1) & 3)) << 4);
            const uint32_t dA = st + row * 64 + sw;
            const uint32_t dB = st + 16384 + row * 64 + sw;
            const size_t so = (size_t)row * (KEL * 2) + kb + c * 16;
            cp16(dA,        pAh + so);
            cp16(dA + 8192, pAl + so);
            cp16(dB,        pBh + so);
            cp16(dB + 8192, pBl + so);
        }
    };

    // Prologue: 2 stages in flight (3rd buffer free for the first prefetch).
    load_stage(0, 0); CP_COMMIT();
    load_stage(1, 1); CP_COMMIT();

    float acc[4][4][4];
    #pragma unroll
    for (int i = 0; i < 4; i++)
        #pragma unroll
        for (int j = 0; j < 4; j++)
            #pragma unroll
            for (int q = 0; q < 4; q++) acc[i][j][q] = 0.0f;

    const int lrow8  = lane & 7;
    const int lhalfA = (lane >> 3) & 1;
    const int lkA    = lane >> 4;
    const int lhalfB = lane >> 4;
    const int lkB    = (lane >> 3) & 1;

    // kt-invariant LDSM offsets (relative to stage base). kc=1 addr = kc=0 ^ 32.
    uint32_t oA[4], oB[2];
    #pragma unroll
    for (int i = 0; i < 4; i++) {
        const int row = wm * 64 + i * 16 + lrow8 + lhalfA * 8;
        oA[i] = row * 64 + ((((uint32_t)lkA) ^ ((row >> 1) & 3)) << 4);
    }
    #pragma unroll
    for (int jp = 0; jp < 2; jp++) {
        const int nrow = wn * 32 + jp * 16 + lrow8 + lhalfB * 8;
        oB[jp] = 16384 + nrow * 64 + ((((uint32_t)lkB) ^ ((nrow >> 1) & 3)) << 4);
    }

    for (int kt = 0; kt < KT; kt++) {
        CP_WAIT1();            // stage kt complete (kt+1 may still be in flight)
        __syncthreads();

        const uint32_t st = sb + (kt % 3) * STAGE_B;
        #pragma unroll
        for (int ks = 0; ks < 2; ks++) {
            const uint32_t kx = (ks == 0) ? 0u : 32u;   // kc offset via XOR

            // ---- B fragments for both jp first (MMAs for i=0 need them) ----
            uint32_t bh[4][2], bl[4][2];
            #pragma unroll
            for (int jp = 0; jp < 2; jp++) {
                const uint32_t bd = st + (oB[jp] ^ kx);
                LDSM_X4(bh[jp*2][0], bh[jp*2][1], bh[jp*2+1][0], bh[jp*2+1][1], bd);
                LDSM_X4(bl[jp*2][0], bl[jp*2][1], bl[jp*2+1][0], bl[jp*2+1][1], bd + 8192);
            }
            // ---- A[0], then interleave A[i+1] under MMAs of A[i] ----
            uint32_t ahf[4][4], alf[4][4];
            {
                const uint32_t ad = st + (oA[0] ^ kx);
                LDSM_X4(ahf[0][0], ahf[0][1], ahf[0][2], ahf[0][3], ad);
                LDSM_X4(alf[0][0], alf[0][1], alf[0][2], alf[0][3], ad + 8192);
            }
            #pragma unroll
            for (int i = 0; i < 4; i++) {
                if (i < 3) {
                    const uint32_t ad = st + (oA[i + 1] ^ kx);
                    LDSM_X4(ahf[i+1][0], ahf[i+1][1], ahf[i+1][2], ahf[i+1][3], ad);
                    LDSM_X4(alf[i+1][0], alf[i+1][1], alf[i+1][2], alf[i+1][3], ad + 8192);
                }
                #pragma unroll
                for (int jp = 0; jp < 2; jp++) {
                    float* c0 = acc[i][jp * 2];
                    float* c1 = acc[i][jp * 2 + 1];
                    MMA16816(c0, ahf[i][0], ahf[i][1], ahf[i][2], ahf[i][3], bh[jp*2][0], bh[jp*2][1]);
                    MMA16816(c0, ahf[i][0], ahf[i][1], ahf[i][2], ahf[i][3], bl[jp*2][0], bl[jp*2][1]);
                    MMA16816(c0, alf[i][0], alf[i][1], alf[i][2], alf[i][3], bh[jp*2][0], bh[jp*2][1]);
                    MMA16816(c1, ahf[i][0], ahf[i][1], ahf[i][2], ahf[i][3], bh[jp*2+1][0], bh[jp*2+1][1]);
                    MMA16816(c1, ahf[i][0], ahf[i][1], ahf[i][2], ahf[i][3], bl[jp*2+1][0], bl[jp*2+1][1]);
                    MMA16816(c1, alf[i][0], alf[i][1], alf[i][2], alf[i][3], bh[jp*2+1][0], bh[jp*2+1][1]);
                }
            }

            // ---- prefetch issued between kc=0 and kc=1, hidden under MMAs ----
            if (ks == 0) {
                if (kt + 2 < KT) load_stage((kt + 2) % 3, kt + 2);
                CP_COMMIT();
            }
        }
    }

    // ---- epilogue -----------------------------------------------------------
    #pragma unroll
    for (int i = 0; i < 4; i++) {
        const size_t r = m0 + wm * 64 + i * 16 + (lane >> 2);
        #pragma unroll
        for (int j = 0; j < 4; j++) {
            const size_t c = n0 + wn * 32 + j * 8 + (lane & 3) * 2;
            *reinterpret_cast<float2*>(C + r * (size_t)Ntot + c) =
                make_float2(acc[i][j][0], acc[i][j][1]);
            *reinterpret_cast<float2*>(C + (r + 8) * (size_t)Ntot + c) =
                make_float2(acc[i][j][2], acc[i][j][3]);
        }
    }
}

// ---------------------------------------------------------------------------
// Merged fp32 -> (hi, lo) bf16 split for x, w1, w2 in ONE launch.
// Group = 8 elements. Segments: x [0, GX), w1 [GX, GX+GW1), w2 [GX+GW1, ...).
// ---------------------------------------------------------------------------
#define GX   ((size_t)MTOK * KEL / 8)        // 4194304
#define GW1  ((size_t)N1 * KEL / 8)          // 1572864
#define GW2  ((size_t)D_MODEL * KEL / 8)     //  524288
#define GTOT (GX + GW1 + GW2)                // 6291456

__global__ __launch_bounds__(256) void split_all(
    const float* __restrict__ x,  const float* __restrict__ w1, const float* __restrict__ w2,
    __nv_bfloat16* __restrict__ xh,  __nv_bfloat16* __restrict__ xl,
    __nv_bfloat16* __restrict__ w1h, __nv_bfloat16* __restrict__ w1l,
    __nv_bfloat16* __restrict__ w2h, __nv_bfloat16* __restrict__ w2l)
{
    size_t g = (size_t)blockIdx.x * blockDim.x + threadIdx.x;
    if (g >= GTOT) return;
    const float* src;
    __nv_bfloat16 *hi, *lo;
    size_t off;
    if (g < GX)            { src = x;  hi = xh;  lo = xl;  off = g; }
    else if (g < GX + GW1) { src = w1; hi = w1h; lo = w1l; off = g - GX; }
    else                   { src = w2; hi = w2h; lo = w2l; off = g - GX - GW1; }

    const float* s = src + off * 8;
    float4 v0 = *reinterpret_cast<const float4*>(s);
    float4 v1 = *reinterpret_cast<const float4*>(s + 4);
    float v[8] = {v0.x, v0.y, v0.z, v0.w, v1.x, v1.y, v1.z, v1.w};
    union { __nv_bfloat16 h[8]; uint4 u; } H, L;
    #pragma unroll
    for (int i = 0; i < 8; i++) {
        __nv_bfloat16 h = __float2bfloat16(v[i]);
        H.h[i] = h;
        L.h[i] = __float2bfloat16(v[i] - __bfloat162float(h));
    }
    *reinterpret_cast<uint4*>(hi + off * 8) = H.u;
    *reinterpret_cast<uint4*>(lo + off * 8) = L.u;
}

// ---------------------------------------------------------------------------
// Fused gate + causal depthwise conv(K=4) + gate; outputs split bf16 u.
// Register-rolling: each thread owns 8 d-cols x 64 consecutive tokens,
// keeps last 3 gated vectors in a 4-slot register ring -> 3 reads/element.
// Strips never cross sequence boundaries (4096 % 64 == 0).
// ---------------------------------------------------------------------------
#define STRIP 64

__global__ __launch_bounds__(256) void conv_gate_roll(
    const float* __restrict__ bcx, const float* __restrict__ cw,
    __nv_bfloat16* __restrict__ uh, __nv_bfloat16* __restrict__ ul)
{
    const int t = blockIdx.x * blockDim.x + threadIdx.x;
    if (t >= (MTOK / STRIP) * 256) return;
    const int dg    = t & 255;          // d-group (8 cols)
    const int strip = t >> 8;
    const int d0 = dg * 8;
    const size_t m0 = (size_t)strip * STRIP;
    const int s0 = (int)(m0 % SEQ);     // within-sequence start

    float w[8][4];
    #pragma unroll
    for (int j = 0; j < 8; j++) {
        float4 wv = *reinterpret_cast<const float4*>(cw + (size_t)(d0 + j) * 4);
        w[j][0] = wv.x; w[j][1] = wv.y; w[j][2] = wv.z; w[j][3] = wv.w;
    }

    // ring slots: g[(tt + q) & 3] holds gated[m0 + tt - 3 + q] for q=0..2,
    // slot (tt+3)&3 receives the current token.
    float g[4][8];
    #pragma unroll
    for (int q = 0; q < 3; q++) {
        #pragma unroll
        for (int j = 0; j < 8; j++) g[q][j] = 0.0f;
        if (s0 > 0) {   // preload gated[m0-3+q]
            const float* row = bcx + (m0 - 3 + q) * (size_t)N1;
            float4 b0 = *reinterpret_cast<const float4*>(row + d0);
            float4 b1 = *reinterpret_cast<const float4*>(row + d0 + 4);
            float4 x0 = *reinterpret_cast<const float4*>(row + 2 * D_MODEL + d0);
            float4 x1 = *reinterpret_cast<const float4*>(row + 2 * D_MODEL + d0 + 4);
            float bb[8] = {b0.x, b0.y, b0.z, b0.w, b1.x, b1.y, b1.z, b1.w};
            float xx[8] = {x0.x, x0.y, x0.z, x0.w, x1.x, x1.y, x1.z, x1.w};
            #pragma unroll
            for (int j = 0; j < 8; j++) g[q][j] = bb[j] * xx[j];
        }
    }

    #pragma unroll 4
    for (int tt = 0; tt < STRIP; tt++) {
        const size_t m = m0 + tt;
        const float* row = bcx + m * (size_t)N1;
        float4 b0 = *reinterpret_cast<const float4*>(row + d0);
        float4 b1 = *reinterpret_cast<const float4*>(row + d0 + 4);
        float4 x0 = *reinterpret_cast<const float4*>(row + 2 * D_MODEL + d0);
        float4 x1 = *reinterpret_cast<const float4*>(row + 2 * D_MODEL + d0 + 4);
        float bb[8] = {b0.x, b0.y, b0.z, b0.w, b1.x, b1.y, b1.z, b1.w};
        float xx[8] = {x0.x, x0.y, x0.z, x0.w, x1.x, x1.y, x1.z, x1.w};
        float* gc = g[(tt + 3) & 3];
        #pragma unroll
        for (int j = 0; j < 8; j++) gc[j] = bb[j] * xx[j];

        const float* g3 = g[tt & 3];        // token m-3
        const float* g2 = g[(tt + 1) & 3];  // token m-2
        const float* g1 = g[(tt + 2) & 3];  // token m-1

        float4 c0 = *reinterpret_cast<const float4*>(row + D_MODEL + d0);
        float4 c1 = *reinterpret_cast<const float4*>(row + D_MODEL + d0 + 4);
        float cc[8] = {c0.x, c0.y, c0.z, c0.w, c1.x, c1.y, c1.z, c1.w};

        union { __nv_bfloat16 h[8]; uint4 u; } H, L;
        #pragma unroll
        for (int j = 0; j < 8; j++) {
            float a = g3[j] * w[j][0];
            a = fmaf(g2[j], w[j][1], a);
            a = fmaf(g1[j], w[j][2], a);
            a = fmaf(gc[j], w[j][3], a);
            float u = cc[j] * a;
            __nv_bfloat16 h = __float2bfloat16(u);
            H.h[j] = h;
            L.h[j] = __float2bfloat16(u - __bfloat162float(h));
        }
        const size_t off = m * (size_t)D_MODEL + d0;
        *reinterpret_cast<uint4*>(uh + off) = H.u;
        *reinterpret_cast<uint4*>(ul + off) = L.u;
    }
}

// ---------------------------------------------------------------------------
extern "C" void kernel_launch(void* const* d_in, const int* in_sizes, int n_in,
                              void* d_out, int out_size)
{
    const float* x  = (const float*)d_in[0];
    const float* w1 = (const float*)d_in[1];
    const float* w2 = (const float*)d_in[2];
    const float* cw = (const float*)d_in[3];
    float* out = (float*)d_out;

    __nv_bfloat16 *xh, *xl, *w1h, *w1l, *w2h, *w2l, *uh, *ul;
    float* bcx;
    cudaGetSymbolAddress((void**)&xh,  g_xh);
    cudaGetSymbolAddress((void**)&xl,  g_xl);
    cudaGetSymbolAddress((void**)&w1h, g_w1h);
    cudaGetSymbolAddress((void**)&w1l, g_w1l);
    cudaGetSymbolAddress((void**)&w2h, g_w2h);
    cudaGetSymbolAddress((void**)&w2l, g_w2l);
    cudaGetSymbolAddress((void**)&uh,  g_uh);
    cudaGetSymbolAddress((void**)&ul,  g_ul);
    cudaGetSymbolAddress((void**)&bcx, g_bcx);

    cudaFuncSetAttribute(gemm_split,
                         cudaFuncAttributeMaxDynamicSharedMemorySize, GEMM_SMEM);

    // One merged split launch for x, w1, w2.
    split_all<<<(int)((GTOT + 255) / 256), 256>>>(
        x, w1, w2, xh, xl, w1h, w1l, w2h, w2l);

    // GEMM1: bcx = x @ w1^T
    {
        dim3 grid(N1 / 128, MTOK / 128);
        gemm_split<<<grid, 256, GEMM_SMEM>>>(xh, xl, w1h, w1l, bcx, N1);
    }

    // fused gate/conv/gate -> uh, ul (register-rolling strips)
    conv_gate_roll<<<((MTOK / STRIP) * 256) / 256, 256>>>(bcx, cw, uh, ul);

    // GEMM2: out = u @ w2^T
    {
        dim3 grid(D_MODEL / 128, MTOK / 128);
        gemm_split<<<grid, 256, GEMM_SMEM>>>(uh, ul, w2h, w2l, out, D_MODEL);
    }
}